// round 11
// baseline (speedup 1.0000x reference)
#include <cuda_runtime.h>
#include <cuda_bf16.h>
#include <math.h>

#define V_N 50000
#define E_N 800000
#define B_N 8
#define H_N 128
#define LAT_N 64
#define TD_N 16
#define LN_EPS 1e-5f
#define PS 136   // padded bf16 row stride (272B) for 128-wide smem tiles
#define EG 10    // edge tiles (64 edges each) per block in k_edge

// ---- scratch (static device globals: allocation-free) ----
__device__ float d_h[(size_t)V_N * H_N];
__device__ float d_agg[(size_t)V_N * H_N];
__device__ float d_xt[(size_t)V_N * 3];
__device__ float d_zc[B_N * H_N];
__device__ float d_cvec[H_N];
__device__ float d_loss;
__device__ __nv_bfloat16 d_Pb[(size_t)V_N * H_N];
__device__ __nv_bfloat16 d_Qb[(size_t)V_N * H_N];
__device__ __nv_bfloat16 d_ew1b[4 * 259 * 128];
__device__ __nv_bfloat16 d_ew2b[4 * 128 * 128];
__device__ __nv_bfloat16 d_nw1b[4 * 256 * 128];
__device__ __nv_bfloat16 d_nw2b[4 * 128 * 128];

__device__ __forceinline__ float silu_f(float x) {
    return __fdividef(x, 1.0f + __expf(-x));
}
__device__ __forceinline__ unsigned pk_bf2(float a, float b) {
    __nv_bfloat162 t = __float22bfloat162_rn(make_float2(a, b));
    return *reinterpret_cast<unsigned*>(&t);
}

// ---------------- mma helpers ----------------
__device__ __forceinline__ void ldsm_x4(unsigned* r, unsigned addr) {
    asm volatile("ldmatrix.sync.aligned.m8n8.x4.shared.b16 {%0,%1,%2,%3}, [%4];"
                 : "=r"(r[0]), "=r"(r[1]), "=r"(r[2]), "=r"(r[3]) : "r"(addr));
}
__device__ __forceinline__ void ldsm_x2t(unsigned* r, unsigned addr) {
    asm volatile("ldmatrix.sync.aligned.m8n8.x2.trans.shared.b16 {%0,%1}, [%2];"
                 : "=r"(r[0]), "=r"(r[1]) : "r"(addr));
}
__device__ __forceinline__ void mma_bf16(float* c, const unsigned* a, const unsigned* b) {
    asm volatile("mma.sync.aligned.m16n8k16.row.col.f32.bf16.bf16.f32 "
                 "{%0,%1,%2,%3},{%4,%5,%6,%7},{%8,%9},{%0,%1,%2,%3};"
                 : "+f"(c[0]), "+f"(c[1]), "+f"(c[2]), "+f"(c[3])
                 : "r"(a[0]), "r"(a[1]), "r"(a[2]), "r"(a[3]), "r"(b[0]), "r"(b[1]));
}

// 128x128x128 bf16 GEMM chunk (8 warps, 64x32 warp tiles)
__device__ __forceinline__ void mma_chunk(float acc[4][4][4],
                                          unsigned aBase, unsigned bBase,
                                          int lane, int R0, int C0) {
    unsigned aRow[4], bCol[4];
    int l15 = lane & 15, lh = lane >> 4;
    #pragma unroll
    for (int mt = 0; mt < 4; mt++)
        aRow[mt] = aBase + (unsigned)((R0 + mt * 16 + l15) * PS + lh * 8) * 2u;
    #pragma unroll
    for (int nt = 0; nt < 4; nt++)
        bCol[nt] = bBase + (unsigned)(l15 * PS + C0 + nt * 8) * 2u;
    #pragma unroll
    for (int ks = 0; ks < 8; ks++) {
        unsigned a[4][4], b[4][2];
        #pragma unroll
        for (int mt = 0; mt < 4; mt++) ldsm_x4(a[mt], aRow[mt] + ks * 32);
        #pragma unroll
        for (int nt = 0; nt < 4; nt++) ldsm_x2t(b[nt], bCol[nt] + ks * (PS * 32));
        #pragma unroll
        for (int mt = 0; mt < 4; mt++)
            #pragma unroll
            for (int nt = 0; nt < 4; nt++)
                mma_bf16(acc[mt][nt], a[mt], b[nt]);
    }
}

// 64x128x128 bf16 GEMM chunk (8 warps, 32x32 warp tiles) — for k_edge
__device__ __forceinline__ void mma_chunk32(float acc[2][4][4],
                                            unsigned aBase, unsigned bBase,
                                            int lane, int R0, int C0) {
    unsigned aRow[2], bCol[4];
    int l15 = lane & 15, lh = lane >> 4;
    #pragma unroll
    for (int mt = 0; mt < 2; mt++)
        aRow[mt] = aBase + (unsigned)((R0 + mt * 16 + l15) * PS + lh * 8) * 2u;
    #pragma unroll
    for (int nt = 0; nt < 4; nt++)
        bCol[nt] = bBase + (unsigned)(l15 * PS + C0 + nt * 8) * 2u;
    #pragma unroll
    for (int ks = 0; ks < 8; ks++) {
        unsigned a[2][4], b[4][2];
        #pragma unroll
        for (int mt = 0; mt < 2; mt++) ldsm_x4(a[mt], aRow[mt] + ks * 32);
        #pragma unroll
        for (int nt = 0; nt < 4; nt++) ldsm_x2t(b[nt], bCol[nt] + ks * (PS * 32));
        #pragma unroll
        for (int mt = 0; mt < 2; mt++)
            #pragma unroll
            for (int nt = 0; nt < 4; nt++)
                mma_bf16(acc[mt][nt], a[mt], b[nt]);
    }
}

// ---------------- fused weight conversion + setup (launch #1) ----------------
__global__ void k_cvtsetup(const float* __restrict__ ew1, const float* __restrict__ ew2,
                           const float* __restrict__ nw1, const float* __restrict__ nw2,
                           const float* __restrict__ t,
                           const float* __restrict__ te_w1, const float* __restrict__ te_b1,
                           const float* __restrict__ te_w2, const float* __restrict__ te_b2,
                           const float* __restrict__ z,
                           const float* __restrict__ cp_w, const float* __restrict__ cp_b) {
    if (blockIdx.x == 0) {
        __shared__ float a_s[TD_N];
        __shared__ float temb[TD_N];
        int tx = threadIdx.x;
        float ts = t[0];
        if (tx < TD_N) a_s[tx] = silu_f(ts * te_w1[tx] + te_b1[tx]);
        __syncthreads();
        if (tx < TD_N) {
            float acc = te_b2[tx];
            #pragma unroll
            for (int j = 0; j < TD_N; j++) acc += a_s[j] * te_w2[j * TD_N + tx];
            temb[tx] = acc;
        }
        __syncthreads();
        if (tx < 128) {
            float acc = cp_b[tx];
            #pragma unroll
            for (int j = 0; j < TD_N; j++) acc += temb[j] * cp_w[(LAT_N + j) * H_N + tx];
            d_cvec[tx] = acc;
            for (int b = 0; b < B_N; b++) {
                float acc2 = 0.f;
                for (int k = 0; k < LAT_N; k++) acc2 += z[b * LAT_N + k] * cp_w[k * H_N + tx];
                d_zc[b * H_N + tx] = acc2;
            }
        }
        if (tx == 0) d_loss = 0.f;
    }
    int i0 = blockIdx.x * blockDim.x + threadIdx.x;
    int st = gridDim.x * blockDim.x;
    for (int i = i0; i < 4 * 259 * 128; i += st) d_ew1b[i] = __float2bfloat16(ew1[i]);
    for (int i = i0; i < 4 * 128 * 128; i += st) d_ew2b[i] = __float2bfloat16(ew2[i]);
    for (int i = i0; i < 4 * 256 * 128; i += st) d_nw1b[i] = __float2bfloat16(nw1[i]);
    for (int i = i0; i < 4 * 128 * 128; i += st) d_nw2b[i] = __float2bfloat16(nw2[i]);
}

// ---------------- init h0 and x_t (launch #2) ----------------
__global__ void k_init(const int* __restrict__ batch,
                       const float* __restrict__ pos0, const float* __restrict__ pos1,
                       const float* __restrict__ t) {
    int node = blockIdx.x * 2 + (threadIdx.x >> 7);
    int c = threadIdx.x & 127;
    if (node >= V_N) return;
    int b = batch[node];
    d_h[(size_t)node * H_N + c] = d_zc[b * H_N + c] + d_cvec[c];
    if (c < 3) {
        float ts = t[0];
        d_xt[node * 3 + c] = (1.f - ts) * pos0[node * 3 + c] + ts * pos1[node * 3 + c];
    }
}

// ---------------- k_pq (layer 0 only): P = h@W1a, Q = h@W1b; zero agg ----------------
__global__ __launch_bounds__(256, 2) void k_pq(const __nv_bfloat16* __restrict__ ew1b_l) {
    extern __shared__ __align__(16) char sm_raw[];
    __nv_bfloat16* sA16 = (__nv_bfloat16*)sm_raw;
    __nv_bfloat16* sB16 = sA16 + 128 * PS;

    int tx = threadIdx.x;
    int vbase = blockIdx.x * 128;
    int lane = tx & 31, wid5 = tx >> 5;
    int R0 = (wid5 >> 2) * 64, C0 = (wid5 & 3) * 32;
    int g = lane >> 2, tig = lane & 3;

    #pragma unroll
    for (int it = 0; it < 8; it++) {
        int i = tx + it * 256;
        int r = i >> 4, c16 = i & 15;
        int v = vbase + r;
        float4 x0 = make_float4(0, 0, 0, 0), x1 = x0;
        if (v < V_N) {
            x0 = ((const float4*)d_h)[(size_t)v * 32 + c16 * 2];
            x1 = ((const float4*)d_h)[(size_t)v * 32 + c16 * 2 + 1];
        }
        unsigned o[4] = {pk_bf2(x0.x, x0.y), pk_bf2(x0.z, x0.w),
                         pk_bf2(x1.x, x1.y), pk_bf2(x1.z, x1.w)};
        *(uint4*)(sA16 + r * PS + c16 * 8) = *(uint4*)o;
    }
    #pragma unroll
    for (int it = 0; it < 8; it++) {
        int i = tx + it * 256;
        int r = i >> 4, c16 = i & 15;
        *(uint4*)(sB16 + r * PS + c16 * 8) = ((const uint4*)ew1b_l)[r * 16 + c16];
    }
    __syncthreads();

    unsigned aBase = (unsigned)__cvta_generic_to_shared(sA16);
    unsigned bBase = (unsigned)__cvta_generic_to_shared(sB16);

    float acc[4][4][4];
    #pragma unroll
    for (int mt = 0; mt < 4; mt++)
        #pragma unroll
        for (int nt = 0; nt < 4; nt++)
            #pragma unroll
            for (int q = 0; q < 4; q++) acc[mt][nt][q] = 0.f;
    mma_chunk(acc, aBase, bBase, lane, R0, C0);
    __syncthreads();

    #pragma unroll
    for (int mt = 0; mt < 4; mt++) {
        int r0 = R0 + mt * 16 + g;
        int v0 = vbase + r0, v1 = v0 + 8;
        #pragma unroll
        for (int nt = 0; nt < 4; nt++) {
            int col = C0 + nt * 8 + tig * 2;
            if (v0 < V_N) *(unsigned*)(d_Pb + (size_t)v0 * 128 + col) = pk_bf2(acc[mt][nt][0], acc[mt][nt][1]);
            if (v1 < V_N) *(unsigned*)(d_Pb + (size_t)v1 * 128 + col) = pk_bf2(acc[mt][nt][2], acc[mt][nt][3]);
            #pragma unroll
            for (int q = 0; q < 4; q++) acc[mt][nt][q] = 0.f;
        }
    }
    const __nv_bfloat16* w1b = ew1b_l + 128 * 128;
    #pragma unroll
    for (int it = 0; it < 8; it++) {
        int i = tx + it * 256;
        int r = i >> 4, c16 = i & 15;
        *(uint4*)(sB16 + r * PS + c16 * 8) = ((const uint4*)w1b)[r * 16 + c16];
    }
    __syncthreads();
    mma_chunk(acc, aBase, bBase, lane, R0, C0);

    #pragma unroll
    for (int mt = 0; mt < 4; mt++) {
        int r0 = R0 + mt * 16 + g;
        int v0 = vbase + r0, v1 = v0 + 8;
        #pragma unroll
        for (int nt = 0; nt < 4; nt++) {
            int col = C0 + nt * 8 + tig * 2;
            if (v0 < V_N) *(unsigned*)(d_Qb + (size_t)v0 * 128 + col) = pk_bf2(acc[mt][nt][0], acc[mt][nt][1]);
            if (v1 < V_N) *(unsigned*)(d_Qb + (size_t)v1 * 128 + col) = pk_bf2(acc[mt][nt][2], acc[mt][nt][3]);
        }
    }
    #pragma unroll
    for (int it = 0; it < 16; it++) {
        int i = tx + it * 256;
        int r = i >> 5, c4 = i & 31;
        int v = vbase + r;
        if (v < V_N) ((float4*)d_agg)[(size_t)v * 32 + c4] = make_float4(0, 0, 0, 0);
    }
}

// ---------------- k_edge: EG x 64-edge tiles per block; W2 loaded ONCE ----------------
__global__ __launch_bounds__(256, 3) void k_edge(const int* __restrict__ ei,
                                                 const float* __restrict__ w1c,
                                                 const float* __restrict__ b1,
                                                 const float* __restrict__ b2,
                                                 const __nv_bfloat16* __restrict__ w2b) {
    extern __shared__ __align__(16) char sm_raw[];
    __nv_bfloat16* sU16 = (__nv_bfloat16*)sm_raw;       // 64 x PS
    __nv_bfloat16* sB16 = sU16 + 64 * PS;               // 128 x PS
    float* sw1c = (float*)(sB16 + 128 * PS);            // 384
    float* sb1  = sw1c + 384;                           // 128
    float* sb2  = sb1 + 128;                            // 128
    float* sdp  = sb2 + 128;                            // 256
    int*   sdst = (int*)(sdp + 256);                    // 64
    int*   ssrc = sdst + 64;                            // 64

    int tx = threadIdx.x;
    int lane = tx & 31, wid5 = tx >> 5;
    int R0 = (wid5 >> 2) * 32, C0 = (wid5 & 3) * 32;
    int g = lane >> 2, tig = lane & 3;

    if (tx < 128) {
        sb1[tx] = b1[tx]; sb2[tx] = b2[tx];
        sw1c[tx] = w1c[tx];
        sw1c[128 + tx] = w1c[128 + tx];
        sw1c[256 + tx] = w1c[256 + tx];
    }
    #pragma unroll
    for (int it = 0; it < 8; it++) {
        int i = tx + it * 256;
        int r = i >> 4, c16 = i & 15;
        *(uint4*)(sB16 + r * PS + c16 * 8) = ((const uint4*)w2b)[r * 16 + c16];
    }

    unsigned aBase = (unsigned)__cvta_generic_to_shared(sU16);
    unsigned bBase = (unsigned)__cvta_generic_to_shared(sB16);

    for (int gtile = 0; gtile < EG; gtile++) {
        int ebase = (blockIdx.x * EG + gtile) * 64;
        __syncthreads();
        if (tx < 64) {
            int e = ebase + tx;
            int s = ei[e];
            int d = ei[E_N + e];
            ssrc[tx] = s; sdst[tx] = d;
            sdp[tx * 4 + 0] = d_xt[d * 3 + 0] - d_xt[s * 3 + 0];
            sdp[tx * 4 + 1] = d_xt[d * 3 + 1] - d_xt[s * 3 + 1];
            sdp[tx * 4 + 2] = d_xt[d * 3 + 2] - d_xt[s * 3 + 2];
        }
        __syncthreads();

        #pragma unroll
        for (int it = 0; it < 4; it++) {
            int i = tx + it * 256;
            int e = i >> 4, c16 = i & 15;
            int c = c16 * 8;
            uint4 pv = *(const uint4*)(d_Pb + (size_t)sdst[e] * 128 + c);
            uint4 qv = *(const uint4*)(d_Qb + (size_t)ssrc[e] * 128 + c);
            __nv_bfloat162* pp = (__nv_bfloat162*)&pv;
            __nv_bfloat162* qq = (__nv_bfloat162*)&qv;
            float dx = sdp[e * 4], dy = sdp[e * 4 + 1], dz = sdp[e * 4 + 2];
            float u[8];
            #pragma unroll
            for (int j = 0; j < 4; j++) {
                float2 pf = __bfloat1622float2(pp[j]);
                float2 qf = __bfloat1622float2(qq[j]);
                int cc = c + j * 2;
                u[j * 2 + 0] = pf.x + qf.x + dx * sw1c[cc] + dy * sw1c[128 + cc] + dz * sw1c[256 + cc] + sb1[cc];
                u[j * 2 + 1] = pf.y + qf.y + dx * sw1c[cc + 1] + dy * sw1c[128 + cc + 1] + dz * sw1c[256 + cc + 1] + sb1[cc + 1];
            }
            unsigned o[4];
            #pragma unroll
            for (int j = 0; j < 4; j++)
                o[j] = pk_bf2(silu_f(u[j * 2]), silu_f(u[j * 2 + 1]));
            *(uint4*)(sU16 + e * PS + c) = *(uint4*)o;
        }
        __syncthreads();

        float acc[2][4][4];
        #pragma unroll
        for (int mt = 0; mt < 2; mt++)
            #pragma unroll
            for (int nt = 0; nt < 4; nt++)
                #pragma unroll
                for (int q = 0; q < 4; q++) acc[mt][nt][q] = 0.f;
        mma_chunk32(acc, aBase, bBase, lane, R0, C0);

        #pragma unroll
        for (int mt = 0; mt < 2; mt++) {
            int r0 = R0 + mt * 16 + g;
            int d0 = sdst[r0], d1 = sdst[r0 + 8];
            #pragma unroll
            for (int nt = 0; nt < 4; nt++) {
                int col = C0 + nt * 8 + tig * 2;
                float bb0 = sb2[col], bb1 = sb2[col + 1];
                float m0 = silu_f(acc[mt][nt][0] + bb0);
                float m1 = silu_f(acc[mt][nt][1] + bb1);
                float m2 = silu_f(acc[mt][nt][2] + bb0);
                float m3 = silu_f(acc[mt][nt][3] + bb1);
                float* pA = d_agg + (size_t)d0 * 128 + col;
                float* pB = d_agg + (size_t)d1 * 128 + col;
                asm volatile("red.global.add.v2.f32 [%0], {%1,%2};" :: "l"(pA), "f"(m0), "f"(m1) : "memory");
                asm volatile("red.global.add.v2.f32 [%0], {%1,%2};" :: "l"(pB), "f"(m2), "f"(m3) : "memory");
            }
        }
    }
}

// ---------------- k_node: MLP + residual + LayerNorm + (fused next-layer P/Q) ----------------
__global__ __launch_bounds__(256, 2) void k_node(const __nv_bfloat16* __restrict__ nw1b_l,
                                                 const float* __restrict__ nb1l,
                                                 const __nv_bfloat16* __restrict__ nw2b_l,
                                                 const float* __restrict__ nb2l,
                                                 const float* __restrict__ lngl,
                                                 const float* __restrict__ lnbl,
                                                 const __nv_bfloat16* __restrict__ ew1b_next) {
    extern __shared__ __align__(16) char sm_raw[];
    __nv_bfloat16* sA16 = (__nv_bfloat16*)sm_raw;           // 128 x PS
    __nv_bfloat16* sB16 = sA16 + 128 * PS;                  // 128 x PS
    float* sPar = (float*)(sB16 + 128 * PS);                // 4 x 128
    float* sb1 = sPar, * sb2 = sPar + 128, * sg = sPar + 256, * sbb = sPar + 384;

    int tx = threadIdx.x;
    int vbase = blockIdx.x * 128;
    int lane = tx & 31, wid5 = tx >> 5;
    int R0 = (wid5 >> 2) * 64, C0 = (wid5 & 3) * 32;
    int g = lane >> 2, tig = lane & 3;

    if (tx < 128) { sb1[tx] = nb1l[tx]; sb2[tx] = nb2l[tx]; sg[tx] = lngl[tx]; sbb[tx] = lnbl[tx]; }

    unsigned aBase = (unsigned)__cvta_generic_to_shared(sA16);
    unsigned bBase = (unsigned)__cvta_generic_to_shared(sB16);

    float acc[4][4][4];
    #pragma unroll
    for (int mt = 0; mt < 4; mt++)
        #pragma unroll
        for (int nt = 0; nt < 4; nt++)
            #pragma unroll
            for (int q = 0; q < 4; q++) acc[mt][nt][q] = 0.f;

    // GEMM1 over K=256: chunk0 = h, chunk1 = agg
    for (int chunk = 0; chunk < 2; chunk++) {
        const float* asrc = chunk ? d_agg : d_h;
        const __nv_bfloat16* wsrc = nw1b_l + chunk * (128 * 128);
        #pragma unroll
        for (int it = 0; it < 8; it++) {
            int i = tx + it * 256;
            int r = i >> 4, c16 = i & 15;
            int v = vbase + r;
            float4 x0 = make_float4(0, 0, 0, 0), x1 = x0;
            if (v < V_N) {
                x0 = ((const float4*)asrc)[(size_t)v * 32 + c16 * 2];
                x1 = ((const float4*)asrc)[(size_t)v * 32 + c16 * 2 + 1];
            }
            unsigned o[4] = {pk_bf2(x0.x, x0.y), pk_bf2(x0.z, x0.w),
                             pk_bf2(x1.x, x1.y), pk_bf2(x1.z, x1.w)};
            *(uint4*)(sA16 + r * PS + c16 * 8) = *(uint4*)o;
        }
        #pragma unroll
        for (int it = 0; it < 8; it++) {
            int i = tx + it * 256;
            int r = i >> 4, c16 = i & 15;
            *(uint4*)(sB16 + r * PS + c16 * 8) = ((const uint4*)wsrc)[r * 16 + c16];
        }
        __syncthreads();
        mma_chunk(acc, aBase, bBase, lane, R0, C0);
        __syncthreads();
    }

    // U = silu(acc + b1) -> sA16 (bf16); B <- nw2
    #pragma unroll
    for (int mt = 0; mt < 4; mt++) {
        int r0 = R0 + mt * 16 + g;
        #pragma unroll
        for (int nt = 0; nt < 4; nt++) {
            int col = C0 + nt * 8 + tig * 2;
            float bb0 = sb1[col], bb1 = sb1[col + 1];
            *(unsigned*)(sA16 + r0 * PS + col) =
                pk_bf2(silu_f(acc[mt][nt][0] + bb0), silu_f(acc[mt][nt][1] + bb1));
            *(unsigned*)(sA16 + (r0 + 8) * PS + col) =
                pk_bf2(silu_f(acc[mt][nt][2] + bb0), silu_f(acc[mt][nt][3] + bb1));
            #pragma unroll
            for (int q = 0; q < 4; q++) acc[mt][nt][q] = 0.f;
        }
    }
    #pragma unroll
    for (int it = 0; it < 8; it++) {
        int i = tx + it * 256;
        int r = i >> 4, c16 = i & 15;
        *(uint4*)(sB16 + r * PS + c16 * 8) = ((const uint4*)nw2b_l)[r * 16 + c16];
    }
    __syncthreads();
    mma_chunk(acc, aBase, bBase, lane, R0, C0);
    __syncthreads();   // done reading sA16 (U); safe to overwrite

    // spill h_new (bf16) into sA16, row stride PS
    #pragma unroll
    for (int mt = 0; mt < 4; mt++) {
        int r0 = R0 + mt * 16 + g;
        #pragma unroll
        for (int nt = 0; nt < 4; nt++) {
            int col = C0 + nt * 8 + tig * 2;
            *(unsigned*)(sA16 + r0 * PS + col) = pk_bf2(acc[mt][nt][0], acc[mt][nt][1]);
            *(unsigned*)(sA16 + (r0 + 8) * PS + col) = pk_bf2(acc[mt][nt][2], acc[mt][nt][3]);
        }
    }
    __syncthreads();

    // residual + LayerNorm; write d_h AND normalized bf16 h back into sA16 in-place
    #pragma unroll 1
    for (int rr = 0; rr < 16; rr++) {
        int row = wid5 * 16 + rr;
        int v = vbase + row;
        if (v >= V_N) break;
        float4 hv = ((const float4*)d_h)[(size_t)v * 32 + lane];
        uint2 hb = *(uint2*)(sA16 + row * PS + lane * 4);
        float2 xa = __bfloat1622float2(*(__nv_bfloat162*)&hb.x);
        float2 xbv = __bfloat1622float2(*(__nv_bfloat162*)&hb.y);
        float4 bb = *(float4*)(sb2 + lane * 4);
        float x0 = hv.x + xa.x + bb.x;
        float x1 = hv.y + xa.y + bb.y;
        float x2 = hv.z + xbv.x + bb.z;
        float x3 = hv.w + xbv.y + bb.w;
        float s1 = x0 + x1 + x2 + x3;
        #pragma unroll
        for (int off = 16; off; off >>= 1) s1 += __shfl_xor_sync(0xffffffffu, s1, off);
        float mu = s1 * (1.f / 128.f);
        float d0 = x0 - mu, d1 = x1 - mu, d2 = x2 - mu, d3 = x3 - mu;
        float s2 = d0 * d0 + d1 * d1 + d2 * d2 + d3 * d3;
        #pragma unroll
        for (int off = 16; off; off >>= 1) s2 += __shfl_xor_sync(0xffffffffu, s2, off);
        float rinv = rsqrtf(s2 * (1.f / 128.f) + LN_EPS);
        float4 gv = *(float4*)(sg + lane * 4);
        float4 bv = *(float4*)(sbb + lane * 4);
        float4 o;
        o.x = gv.x * d0 * rinv + bv.x;
        o.y = gv.y * d1 * rinv + bv.y;
        o.z = gv.z * d2 * rinv + bv.z;
        o.w = gv.w * d3 * rinv + bv.w;
        ((float4*)d_h)[(size_t)v * 32 + lane] = o;
        uint2 ob;
        ob.x = pk_bf2(o.x, o.y);
        ob.y = pk_bf2(o.z, o.w);
        *(uint2*)(sA16 + row * PS + lane * 4) = ob;
    }

    // ---- fused next-layer P/Q + agg zeroing ----
    if (ew1b_next) {
        __syncthreads();   // sA16 holds normalized h bf16
        #pragma unroll
        for (int it = 0; it < 8; it++) {
            int i = tx + it * 256;
            int r = i >> 4, c16 = i & 15;
            *(uint4*)(sB16 + r * PS + c16 * 8) = ((const uint4*)ew1b_next)[r * 16 + c16];
        }
        __syncthreads();

        #pragma unroll
        for (int mt = 0; mt < 4; mt++)
            #pragma unroll
            for (int nt = 0; nt < 4; nt++)
                #pragma unroll
                for (int q = 0; q < 4; q++) acc[mt][nt][q] = 0.f;
        mma_chunk(acc, aBase, bBase, lane, R0, C0);
        __syncthreads();

        #pragma unroll
        for (int mt = 0; mt < 4; mt++) {
            int r0 = R0 + mt * 16 + g;
            int v0 = vbase + r0, v1 = v0 + 8;
            #pragma unroll
            for (int nt = 0; nt < 4; nt++) {
                int col = C0 + nt * 8 + tig * 2;
                if (v0 < V_N) *(unsigned*)(d_Pb + (size_t)v0 * 128 + col) = pk_bf2(acc[mt][nt][0], acc[mt][nt][1]);
                if (v1 < V_N) *(unsigned*)(d_Pb + (size_t)v1 * 128 + col) = pk_bf2(acc[mt][nt][2], acc[mt][nt][3]);
                #pragma unroll
                for (int q = 0; q < 4; q++) acc[mt][nt][q] = 0.f;
            }
        }
        const __nv_bfloat16* w1b = ew1b_next + 128 * 128;
        #pragma unroll
        for (int it = 0; it < 8; it++) {
            int i = tx + it * 256;
            int r = i >> 4, c16 = i & 15;
            *(uint4*)(sB16 + r * PS + c16 * 8) = ((const uint4*)w1b)[r * 16 + c16];
        }
        __syncthreads();
        mma_chunk(acc, aBase, bBase, lane, R0, C0);

        #pragma unroll
        for (int mt = 0; mt < 4; mt++) {
            int r0 = R0 + mt * 16 + g;
            int v0 = vbase + r0, v1 = v0 + 8;
            #pragma unroll
            for (int nt = 0; nt < 4; nt++) {
                int col = C0 + nt * 8 + tig * 2;
                if (v0 < V_N) *(unsigned*)(d_Qb + (size_t)v0 * 128 + col) = pk_bf2(acc[mt][nt][0], acc[mt][nt][1]);
                if (v1 < V_N) *(unsigned*)(d_Qb + (size_t)v1 * 128 + col) = pk_bf2(acc[mt][nt][2], acc[mt][nt][3]);
            }
        }
        // zero agg for next layer
        #pragma unroll
        for (int it = 0; it < 16; it++) {
            int i = tx + it * 256;
            int r = i >> 5, c4 = i & 31;
            int v = vbase + r;
            if (v < V_N) ((float4*)d_agg)[(size_t)v * 32 + c4] = make_float4(0, 0, 0, 0);
        }
    }
}

// ---------------- final loss ----------------
__global__ void k_loss(const float* __restrict__ pos0, const float* __restrict__ pos1,
                       const float* __restrict__ op_w, const float* __restrict__ op_b) {
    int lane = threadIdx.x & 31;
    int warp = threadIdx.x >> 5;
    int gw = blockIdx.x * 8 + warp;
    int nw = gridDim.x * 8;
    float local = 0.f;
    for (int v = gw; v < V_N; v += nw) {
        float s0 = 0.f, s1 = 0.f, s2 = 0.f;
        #pragma unroll
        for (int k = 0; k < 4; k++) {
            int c = lane + k * 32;
            float hv = d_h[(size_t)v * 128 + c];
            s0 = fmaf(hv, op_w[c * 3 + 0], s0);
            s1 = fmaf(hv, op_w[c * 3 + 1], s1);
            s2 = fmaf(hv, op_w[c * 3 + 2], s2);
        }
        #pragma unroll
        for (int off = 16; off; off >>= 1) {
            s0 += __shfl_xor_sync(0xffffffffu, s0, off);
            s1 += __shfl_xor_sync(0xffffffffu, s1, off);
            s2 += __shfl_xor_sync(0xffffffffu, s2, off);
        }
        if (lane == 0) {
            float d0 = s0 + op_b[0] - (pos1[v * 3 + 0] - pos0[v * 3 + 0]);
            float d1 = s1 + op_b[1] - (pos1[v * 3 + 1] - pos0[v * 3 + 1]);
            float d2 = s2 + op_b[2] - (pos1[v * 3 + 2] - pos0[v * 3 + 2]);
            local += d0 * d0 + d1 * d1 + d2 * d2;
        }
    }
    __shared__ float ws[8];
    if (lane == 0) ws[warp] = local;
    __syncthreads();
    if (threadIdx.x == 0) {
        float s = 0.f;
        for (int w = 0; w < 8; w++) s += ws[w];
        atomicAdd(&d_loss, s);
    }
}

__global__ void k_final(float* out) {
    out[0] = d_loss * (1.f / (3.f * (float)V_N));
}

// ---------------- launcher ----------------
extern "C" void kernel_launch(void* const* d_in, const int* in_sizes, int n_in,
                              void* d_out, int out_size) {
    const float* pos0  = (const float*)d_in[0];
    const float* pos1  = (const float*)d_in[1];
    const float* z     = (const float*)d_in[2];
    const float* t     = (const float*)d_in[3];
    const int*   ei    = (const int*)d_in[4];
    const int*   batch = (const int*)d_in[5];
    const float* te_w1 = (const float*)d_in[6];
    const float* te_b1 = (const float*)d_in[7];
    const float* te_w2 = (const float*)d_in[8];
    const float* te_b2 = (const float*)d_in[9];
    const float* cp_w  = (const float*)d_in[10];
    const float* cp_b  = (const float*)d_in[11];
    const float* ew1   = (const float*)d_in[12];
    const float* eb1   = (const float*)d_in[13];
    const float* ew2   = (const float*)d_in[14];
    const float* eb2   = (const float*)d_in[15];
    const float* nw1   = (const float*)d_in[16];
    const float* nb1   = (const float*)d_in[17];
    const float* nw2   = (const float*)d_in[18];
    const float* nb2   = (const float*)d_in[19];
    const float* ln_g  = (const float*)d_in[20];
    const float* ln_b  = (const float*)d_in[21];
    const float* op_w  = (const float*)d_in[22];
    const float* op_b  = (const float*)d_in[23];

    const int SMEM_PQ   = 128 * PS * 2 * 2;                                     // 69632
    const int SMEM_EDGE = 64 * PS * 2 + 128 * PS * 2 + (384 + 256 + 256) * 4 + 512 + 512; // 56832
    const int SMEM_NODE = 128 * PS * 2 * 2 + 4 * 128 * 4;                       // 71680

    cudaFuncSetAttribute(k_pq,   cudaFuncAttributeMaxDynamicSharedMemorySize, SMEM_PQ);
    cudaFuncSetAttribute(k_edge, cudaFuncAttributeMaxDynamicSharedMemorySize, SMEM_EDGE);
    cudaFuncSetAttribute(k_node, cudaFuncAttributeMaxDynamicSharedMemorySize, SMEM_NODE);

    __nv_bfloat16 *ew1b_base, *ew2b_base, *nw1b_base, *nw2b_base;
    cudaGetSymbolAddress((void**)&ew1b_base, d_ew1b);
    cudaGetSymbolAddress((void**)&ew2b_base, d_ew2b);
    cudaGetSymbolAddress((void**)&nw1b_base, d_nw1b);
    cudaGetSymbolAddress((void**)&nw2b_base, d_nw2b);

    // launch order: k_edge is the 4th launch (ncu window)
    k_cvtsetup<<<256, 256>>>(ew1, ew2, nw1, nw2, t, te_w1, te_b1, te_w2, te_b2, z, cp_w, cp_b);
    k_init<<<V_N / 2, 256>>>(batch, pos0, pos1, t);

    int nodeblocks = (V_N + 127) / 128;  // 391
    k_pq<<<nodeblocks, 256, SMEM_PQ>>>(ew1b_base);   // layer 0 P/Q + agg zero
    for (int l = 0; l < 4; l++) {
        k_edge<<<E_N / (64 * EG), 256, SMEM_EDGE>>>(ei,
                                                    ew1 + (size_t)l * 259 * 128 + 256 * 128,
                                                    eb1 + l * 128,
                                                    eb2 + l * 128,
                                                    ew2b_base + (size_t)l * 128 * 128);
        const __nv_bfloat16* nxt = (l < 3) ? (ew1b_base + (size_t)(l + 1) * 259 * 128)
                                           : (const __nv_bfloat16*)nullptr;
        k_node<<<nodeblocks, 256, SMEM_NODE>>>(nw1b_base + (size_t)l * 256 * 128, nb1 + l * 128,
                                               nw2b_base + (size_t)l * 128 * 128, nb2 + l * 128,
                                               ln_g + l * 128, ln_b + l * 128, nxt);
    }
    k_loss<<<592, 256>>>(pos0, pos1, op_w, op_b);
    k_final<<<1, 1>>>((float*)d_out);
}

// round 12
// speedup vs baseline: 1.0957x; 1.0957x over previous
#include <cuda_runtime.h>
#include <cuda_bf16.h>
#include <math.h>

#define V_N 50000
#define E_N 800000
#define B_N 8
#define H_N 128
#define LAT_N 64
#define TD_N 16
#define LN_EPS 1e-5f
#define PS 136   // padded bf16 row stride (272B) for 128-wide smem tiles
#define EG 4     // edge tiles (64 edges each) per block in k_edge

// ---- scratch (static device globals: allocation-free) ----
__device__ float d_h[(size_t)V_N * H_N];
__device__ float d_agg[(size_t)V_N * H_N];
__device__ float d_xt[(size_t)V_N * 3];
__device__ float d_zc[B_N * H_N];
__device__ float d_cvec[H_N];
__device__ float d_loss;
__device__ __nv_bfloat16 d_Pb[(size_t)V_N * H_N];
__device__ __nv_bfloat16 d_Qb[(size_t)V_N * H_N];
__device__ __nv_bfloat16 d_ew1b[4 * 259 * 128];
__device__ __nv_bfloat16 d_ew2b[4 * 128 * 128];
__device__ __nv_bfloat16 d_nw1b[4 * 256 * 128];
__device__ __nv_bfloat16 d_nw2b[4 * 128 * 128];

__device__ __forceinline__ float silu_f(float x) {
    return __fdividef(x, 1.0f + __expf(-x));
}
__device__ __forceinline__ unsigned pk_bf2(float a, float b) {
    __nv_bfloat162 t = __float22bfloat162_rn(make_float2(a, b));
    return *reinterpret_cast<unsigned*>(&t);
}

// ---------------- mma helpers ----------------
__device__ __forceinline__ void ldsm_x4(unsigned* r, unsigned addr) {
    asm volatile("ldmatrix.sync.aligned.m8n8.x4.shared.b16 {%0,%1,%2,%3}, [%4];"
                 : "=r"(r[0]), "=r"(r[1]), "=r"(r[2]), "=r"(r[3]) : "r"(addr));
}
__device__ __forceinline__ void ldsm_x2t(unsigned* r, unsigned addr) {
    asm volatile("ldmatrix.sync.aligned.m8n8.x2.trans.shared.b16 {%0,%1}, [%2];"
                 : "=r"(r[0]), "=r"(r[1]) : "r"(addr));
}
__device__ __forceinline__ void mma_bf16(float* c, const unsigned* a, const unsigned* b) {
    asm volatile("mma.sync.aligned.m16n8k16.row.col.f32.bf16.bf16.f32 "
                 "{%0,%1,%2,%3},{%4,%5,%6,%7},{%8,%9},{%0,%1,%2,%3};"
                 : "+f"(c[0]), "+f"(c[1]), "+f"(c[2]), "+f"(c[3])
                 : "r"(a[0]), "r"(a[1]), "r"(a[2]), "r"(a[3]), "r"(b[0]), "r"(b[1]));
}

// 128x128x128 bf16 GEMM chunk (8 warps, 64x32 warp tiles)
__device__ __forceinline__ void mma_chunk(float acc[4][4][4],
                                          unsigned aBase, unsigned bBase,
                                          int lane, int R0, int C0) {
    unsigned aRow[4], bCol[4];
    int l15 = lane & 15, lh = lane >> 4;
    #pragma unroll
    for (int mt = 0; mt < 4; mt++)
        aRow[mt] = aBase + (unsigned)((R0 + mt * 16 + l15) * PS + lh * 8) * 2u;
    #pragma unroll
    for (int nt = 0; nt < 4; nt++)
        bCol[nt] = bBase + (unsigned)(l15 * PS + C0 + nt * 8) * 2u;
    #pragma unroll
    for (int ks = 0; ks < 8; ks++) {
        unsigned a[4][4], b[4][2];
        #pragma unroll
        for (int mt = 0; mt < 4; mt++) ldsm_x4(a[mt], aRow[mt] + ks * 32);
        #pragma unroll
        for (int nt = 0; nt < 4; nt++) ldsm_x2t(b[nt], bCol[nt] + ks * (PS * 32));
        #pragma unroll
        for (int mt = 0; mt < 4; mt++)
            #pragma unroll
            for (int nt = 0; nt < 4; nt++)
                mma_bf16(acc[mt][nt], a[mt], b[nt]);
    }
}

// 64x128x128 bf16 GEMM chunk (8 warps, 32x32 warp tiles) — for k_edge
__device__ __forceinline__ void mma_chunk32(float acc[2][4][4],
                                            unsigned aBase, unsigned bBase,
                                            int lane, int R0, int C0) {
    unsigned aRow[2], bCol[4];
    int l15 = lane & 15, lh = lane >> 4;
    #pragma unroll
    for (int mt = 0; mt < 2; mt++)
        aRow[mt] = aBase + (unsigned)((R0 + mt * 16 + l15) * PS + lh * 8) * 2u;
    #pragma unroll
    for (int nt = 0; nt < 4; nt++)
        bCol[nt] = bBase + (unsigned)(l15 * PS + C0 + nt * 8) * 2u;
    #pragma unroll
    for (int ks = 0; ks < 8; ks++) {
        unsigned a[2][4], b[4][2];
        #pragma unroll
        for (int mt = 0; mt < 2; mt++) ldsm_x4(a[mt], aRow[mt] + ks * 32);
        #pragma unroll
        for (int nt = 0; nt < 4; nt++) ldsm_x2t(b[nt], bCol[nt] + ks * (PS * 32));
        #pragma unroll
        for (int mt = 0; mt < 2; mt++)
            #pragma unroll
            for (int nt = 0; nt < 4; nt++)
                mma_bf16(acc[mt][nt], a[mt], b[nt]);
    }
}

// ---------------- weight conversion (launch #1) ----------------
__global__ void k_cvt(const float* __restrict__ ew1, const float* __restrict__ ew2,
                      const float* __restrict__ nw1, const float* __restrict__ nw2) {
    int i0 = blockIdx.x * blockDim.x + threadIdx.x;
    int st = gridDim.x * blockDim.x;
    for (int i = i0; i < 4 * 259 * 128; i += st) d_ew1b[i] = __float2bfloat16(ew1[i]);
    for (int i = i0; i < 4 * 128 * 128; i += st) d_ew2b[i] = __float2bfloat16(ew2[i]);
    for (int i = i0; i < 4 * 256 * 128; i += st) d_nw1b[i] = __float2bfloat16(nw1[i]);
    for (int i = i0; i < 4 * 128 * 128; i += st) d_nw2b[i] = __float2bfloat16(nw2[i]);
}

// ---------------- setup: time embedding, cond-proj folding (launch #2) ----------------
__global__ void k_setup(const float* __restrict__ t,
                        const float* __restrict__ te_w1, const float* __restrict__ te_b1,
                        const float* __restrict__ te_w2, const float* __restrict__ te_b2,
                        const float* __restrict__ z,
                        const float* __restrict__ cp_w, const float* __restrict__ cp_b) {
    __shared__ float a_s[TD_N];
    __shared__ float temb[TD_N];
    int tx = threadIdx.x;  // 128 threads
    float ts = t[0];
    if (tx < TD_N) a_s[tx] = silu_f(ts * te_w1[tx] + te_b1[tx]);
    __syncthreads();
    if (tx < TD_N) {
        float acc = te_b2[tx];
        #pragma unroll
        for (int j = 0; j < TD_N; j++) acc += a_s[j] * te_w2[j * TD_N + tx];
        temb[tx] = acc;
    }
    __syncthreads();
    {
        float acc = cp_b[tx];
        #pragma unroll
        for (int j = 0; j < TD_N; j++) acc += temb[j] * cp_w[(LAT_N + j) * H_N + tx];
        d_cvec[tx] = acc;
    }
    for (int b = 0; b < B_N; b++) {
        float acc = 0.f;
        for (int k = 0; k < LAT_N; k++) acc += z[b * LAT_N + k] * cp_w[k * H_N + tx];
        d_zc[b * H_N + tx] = acc;
    }
    if (tx == 0) d_loss = 0.f;
}

// ---------------- k_pq: P = h@W1a, Q = h@W1b; zero agg; layer0 also inits h/xt ----------------
__global__ __launch_bounds__(256, 2) void k_pq(const __nv_bfloat16* __restrict__ ew1b_l,
                                               const int* __restrict__ batch,
                                               const float* __restrict__ pos0,
                                               const float* __restrict__ pos1,
                                               const float* __restrict__ t,
                                               int init) {
    extern __shared__ __align__(16) char sm_raw[];
    __nv_bfloat16* sA16 = (__nv_bfloat16*)sm_raw;
    __nv_bfloat16* sB16 = sA16 + 128 * PS;

    int tx = threadIdx.x;
    int vbase = blockIdx.x * 128;
    int lane = tx & 31, wid5 = tx >> 5;
    int R0 = (wid5 >> 2) * 64, C0 = (wid5 & 3) * 32;
    int g = lane >> 2, tig = lane & 3;

    // fill A: layer 0 computes h0 = zc[batch] + cvec inline (and writes d_h);
    // later layers read d_h.
    #pragma unroll
    for (int it = 0; it < 8; it++) {
        int i = tx + it * 256;
        int r = i >> 4, c16 = i & 15;
        int v = vbase + r;
        float4 x0 = make_float4(0, 0, 0, 0), x1 = x0;
        if (v < V_N) {
            if (init) {
                int b = batch[v];
                float4 z0 = ((const float4*)d_zc)[b * 32 + c16 * 2];
                float4 z1 = ((const float4*)d_zc)[b * 32 + c16 * 2 + 1];
                float4 c0 = ((const float4*)d_cvec)[c16 * 2];
                float4 c1 = ((const float4*)d_cvec)[c16 * 2 + 1];
                x0 = make_float4(z0.x + c0.x, z0.y + c0.y, z0.z + c0.z, z0.w + c0.w);
                x1 = make_float4(z1.x + c1.x, z1.y + c1.y, z1.z + c1.z, z1.w + c1.w);
                ((float4*)d_h)[(size_t)v * 32 + c16 * 2] = x0;
                ((float4*)d_h)[(size_t)v * 32 + c16 * 2 + 1] = x1;
            } else {
                x0 = ((const float4*)d_h)[(size_t)v * 32 + c16 * 2];
                x1 = ((const float4*)d_h)[(size_t)v * 32 + c16 * 2 + 1];
            }
        }
        unsigned o[4] = {pk_bf2(x0.x, x0.y), pk_bf2(x0.z, x0.w),
                         pk_bf2(x1.x, x1.y), pk_bf2(x1.z, x1.w)};
        *(uint4*)(sA16 + r * PS + c16 * 8) = *(uint4*)o;
    }
    if (init && tx < 128) {
        int v = vbase + tx;
        if (v < V_N) {
            float ts = t[0];
            #pragma unroll
            for (int c = 0; c < 3; c++)
                d_xt[v * 3 + c] = (1.f - ts) * pos0[v * 3 + c] + ts * pos1[v * 3 + c];
        }
    }
    #pragma unroll
    for (int it = 0; it < 8; it++) {
        int i = tx + it * 256;
        int r = i >> 4, c16 = i & 15;
        *(uint4*)(sB16 + r * PS + c16 * 8) = ((const uint4*)ew1b_l)[r * 16 + c16];
    }
    __syncthreads();

    unsigned aBase = (unsigned)__cvta_generic_to_shared(sA16);
    unsigned bBase = (unsigned)__cvta_generic_to_shared(sB16);

    float acc[4][4][4];
    #pragma unroll
    for (int mt = 0; mt < 4; mt++)
        #pragma unroll
        for (int nt = 0; nt < 4; nt++)
            #pragma unroll
            for (int q = 0; q < 4; q++) acc[mt][nt][q] = 0.f;
    mma_chunk(acc, aBase, bBase, lane, R0, C0);
    __syncthreads();

    #pragma unroll
    for (int mt = 0; mt < 4; mt++) {
        int r0 = R0 + mt * 16 + g;
        int v0 = vbase + r0, v1 = v0 + 8;
        #pragma unroll
        for (int nt = 0; nt < 4; nt++) {
            int col = C0 + nt * 8 + tig * 2;
            if (v0 < V_N) *(unsigned*)(d_Pb + (size_t)v0 * 128 + col) = pk_bf2(acc[mt][nt][0], acc[mt][nt][1]);
            if (v1 < V_N) *(unsigned*)(d_Pb + (size_t)v1 * 128 + col) = pk_bf2(acc[mt][nt][2], acc[mt][nt][3]);
            #pragma unroll
            for (int q = 0; q < 4; q++) acc[mt][nt][q] = 0.f;
        }
    }
    const __nv_bfloat16* w1b = ew1b_l + 128 * 128;
    #pragma unroll
    for (int it = 0; it < 8; it++) {
        int i = tx + it * 256;
        int r = i >> 4, c16 = i & 15;
        *(uint4*)(sB16 + r * PS + c16 * 8) = ((const uint4*)w1b)[r * 16 + c16];
    }
    __syncthreads();
    mma_chunk(acc, aBase, bBase, lane, R0, C0);

    #pragma unroll
    for (int mt = 0; mt < 4; mt++) {
        int r0 = R0 + mt * 16 + g;
        int v0 = vbase + r0, v1 = v0 + 8;
        #pragma unroll
        for (int nt = 0; nt < 4; nt++) {
            int col = C0 + nt * 8 + tig * 2;
            if (v0 < V_N) *(unsigned*)(d_Qb + (size_t)v0 * 128 + col) = pk_bf2(acc[mt][nt][0], acc[mt][nt][1]);
            if (v1 < V_N) *(unsigned*)(d_Qb + (size_t)v1 * 128 + col) = pk_bf2(acc[mt][nt][2], acc[mt][nt][3]);
        }
    }
    #pragma unroll
    for (int it = 0; it < 16; it++) {
        int i = tx + it * 256;
        int r = i >> 5, c4 = i & 31;
        int v = vbase + r;
        if (v < V_N) ((float4*)d_agg)[(size_t)v * 32 + c4] = make_float4(0, 0, 0, 0);
    }
}

// ---------------- k_edge: EG x 64-edge tiles; W2 once; pipelined index prefetch ----------------
__global__ __launch_bounds__(256, 3) void k_edge(const int* __restrict__ ei,
                                                 const float* __restrict__ w1c,
                                                 const float* __restrict__ b1,
                                                 const float* __restrict__ b2,
                                                 const __nv_bfloat16* __restrict__ w2b) {
    extern __shared__ __align__(16) char sm_raw[];
    __nv_bfloat16* sU16 = (__nv_bfloat16*)sm_raw;       // 64 x PS
    __nv_bfloat16* sB16 = sU16 + 64 * PS;               // 128 x PS
    float* sw1c = (float*)(sB16 + 128 * PS);            // 384
    float* sb1  = sw1c + 384;                           // 128
    float* sb2  = sb1 + 128;                            // 128
    float* sdp  = sb2 + 128;                            // 2 x 256 (double-buffered)
    int*   sdst = (int*)(sdp + 512);                    // 2 x 64
    int*   ssrc = sdst + 128;                           // 2 x 64

    int tx = threadIdx.x;
    int lane = tx & 31, wid5 = tx >> 5;
    int R0 = (wid5 >> 2) * 32, C0 = (wid5 & 3) * 32;
    int g = lane >> 2, tig = lane & 3;

    if (tx < 128) {
        sb1[tx] = b1[tx]; sb2[tx] = b2[tx];
        sw1c[tx] = w1c[tx];
        sw1c[128 + tx] = w1c[128 + tx];
        sw1c[256 + tx] = w1c[256 + tx];
    }
    #pragma unroll
    for (int it = 0; it < 8; it++) {
        int i = tx + it * 256;
        int r = i >> 4, c16 = i & 15;
        *(uint4*)(sB16 + r * PS + c16 * 8) = ((const uint4*)w2b)[r * 16 + c16];
    }
    // prefetch tile 0 indices
    if (tx < 64) {
        int e = blockIdx.x * EG * 64 + tx;
        int s = ei[e];
        int d = ei[E_N + e];
        ssrc[tx] = s; sdst[tx] = d;
        sdp[tx * 4 + 0] = d_xt[d * 3 + 0] - d_xt[s * 3 + 0];
        sdp[tx * 4 + 1] = d_xt[d * 3 + 1] - d_xt[s * 3 + 1];
        sdp[tx * 4 + 2] = d_xt[d * 3 + 2] - d_xt[s * 3 + 2];
    }
    __syncthreads();

    unsigned aBase = (unsigned)__cvta_generic_to_shared(sU16);
    unsigned bBase = (unsigned)__cvta_generic_to_shared(sB16);

    for (int gtile = 0; gtile < EG; gtile++) {
        int cur = gtile & 1, nxt = cur ^ 1;
        const int* cdst = sdst + cur * 64;
        const int* csrc = ssrc + cur * 64;
        const float* cdp = sdp + cur * 256;

        // gather + fused first layer: U = silu(P[dst] + Q[src] + dpos@W1c + b1)
        #pragma unroll
        for (int it = 0; it < 4; it++) {
            int i = tx + it * 256;
            int e = i >> 4, c16 = i & 15;
            int c = c16 * 8;
            uint4 pv = *(const uint4*)(d_Pb + (size_t)cdst[e] * 128 + c);
            uint4 qv = *(const uint4*)(d_Qb + (size_t)csrc[e] * 128 + c);
            __nv_bfloat162* pp = (__nv_bfloat162*)&pv;
            __nv_bfloat162* qq = (__nv_bfloat162*)&qv;
            float dx = cdp[e * 4], dy = cdp[e * 4 + 1], dz = cdp[e * 4 + 2];
            float u[8];
            #pragma unroll
            for (int j = 0; j < 4; j++) {
                float2 pf = __bfloat1622float2(pp[j]);
                float2 qf = __bfloat1622float2(qq[j]);
                int cc = c + j * 2;
                u[j * 2 + 0] = pf.x + qf.x + dx * sw1c[cc] + dy * sw1c[128 + cc] + dz * sw1c[256 + cc] + sb1[cc];
                u[j * 2 + 1] = pf.y + qf.y + dx * sw1c[cc + 1] + dy * sw1c[128 + cc + 1] + dz * sw1c[256 + cc + 1] + sb1[cc + 1];
            }
            unsigned o[4];
            #pragma unroll
            for (int j = 0; j < 4; j++)
                o[j] = pk_bf2(silu_f(u[j * 2]), silu_f(u[j * 2 + 1]));
            *(uint4*)(sU16 + e * PS + c) = *(uint4*)o;
        }
        __syncthreads();

        // prefetch next tile's indices/dpos into the other buffer (overlaps mma)
        if (gtile + 1 < EG && tx < 64) {
            int e = (blockIdx.x * EG + gtile + 1) * 64 + tx;
            int s = ei[e];
            int d = ei[E_N + e];
            ssrc[nxt * 64 + tx] = s; sdst[nxt * 64 + tx] = d;
            sdp[nxt * 256 + tx * 4 + 0] = d_xt[d * 3 + 0] - d_xt[s * 3 + 0];
            sdp[nxt * 256 + tx * 4 + 1] = d_xt[d * 3 + 1] - d_xt[s * 3 + 1];
            sdp[nxt * 256 + tx * 4 + 2] = d_xt[d * 3 + 2] - d_xt[s * 3 + 2];
        }

        float acc[2][4][4];
        #pragma unroll
        for (int mt = 0; mt < 2; mt++)
            #pragma unroll
            for (int nt = 0; nt < 4; nt++)
                #pragma unroll
                for (int q = 0; q < 4; q++) acc[mt][nt][q] = 0.f;
        mma_chunk32(acc, aBase, bBase, lane, R0, C0);

        // epilogue: silu + v2 REDs into agg
        #pragma unroll
        for (int mt = 0; mt < 2; mt++) {
            int r0 = R0 + mt * 16 + g;
            int d0 = cdst[r0], d1 = cdst[r0 + 8];
            #pragma unroll
            for (int nt = 0; nt < 4; nt++) {
                int col = C0 + nt * 8 + tig * 2;
                float bb0 = sb2[col], bb1 = sb2[col + 1];
                float m0 = silu_f(acc[mt][nt][0] + bb0);
                float m1 = silu_f(acc[mt][nt][1] + bb1);
                float m2 = silu_f(acc[mt][nt][2] + bb0);
                float m3 = silu_f(acc[mt][nt][3] + bb1);
                float* pA = d_agg + (size_t)d0 * 128 + col;
                float* pB = d_agg + (size_t)d1 * 128 + col;
                asm volatile("red.global.add.v2.f32 [%0], {%1,%2};" :: "l"(pA), "f"(m0), "f"(m1) : "memory");
                asm volatile("red.global.add.v2.f32 [%0], {%1,%2};" :: "l"(pB), "f"(m2), "f"(m3) : "memory");
            }
        }
        __syncthreads();   // mma readers + prefetch done before next U-build overwrites sU16
    }
}

// ---------------- k_node: MLP (bf16 mma) + residual + LayerNorm ----------------
__global__ __launch_bounds__(256, 2) void k_node(const __nv_bfloat16* __restrict__ nw1b_l,
                                                 const float* __restrict__ nb1l,
                                                 const __nv_bfloat16* __restrict__ nw2b_l,
                                                 const float* __restrict__ nb2l,
                                                 const float* __restrict__ lngl,
                                                 const float* __restrict__ lnbl) {
    extern __shared__ __align__(16) char sm_raw[];
    __nv_bfloat16* sA16 = (__nv_bfloat16*)sm_raw;           // 128 x PS
    __nv_bfloat16* sB16 = sA16 + 128 * PS;                  // 128 x PS
    float* sPar = (float*)(sB16 + 128 * PS);                // 4 x 128
    float* sb1 = sPar, * sb2 = sPar + 128, * sg = sPar + 256, * sbb = sPar + 384;
    float* sX = (float*)sm_raw;                             // aliases A/B: 128 x 132 fp32

    int tx = threadIdx.x;
    int vbase = blockIdx.x * 128;
    int lane = tx & 31, wid5 = tx >> 5;
    int R0 = (wid5 >> 2) * 64, C0 = (wid5 & 3) * 32;
    int g = lane >> 2, tig = lane & 3;

    if (tx < 128) { sb1[tx] = nb1l[tx]; sb2[tx] = nb2l[tx]; sg[tx] = lngl[tx]; sbb[tx] = lnbl[tx]; }

    unsigned aBase = (unsigned)__cvta_generic_to_shared(sA16);
    unsigned bBase = (unsigned)__cvta_generic_to_shared(sB16);

    float acc[4][4][4];
    #pragma unroll
    for (int mt = 0; mt < 4; mt++)
        #pragma unroll
        for (int nt = 0; nt < 4; nt++)
            #pragma unroll
            for (int q = 0; q < 4; q++) acc[mt][nt][q] = 0.f;

    for (int chunk = 0; chunk < 2; chunk++) {
        const float* asrc = chunk ? d_agg : d_h;
        const __nv_bfloat16* wsrc = nw1b_l + chunk * (128 * 128);
        #pragma unroll
        for (int it = 0; it < 8; it++) {
            int i = tx + it * 256;
            int r = i >> 4, c16 = i & 15;
            int v = vbase + r;
            float4 x0 = make_float4(0, 0, 0, 0), x1 = x0;
            if (v < V_N) {
                x0 = ((const float4*)asrc)[(size_t)v * 32 + c16 * 2];
                x1 = ((const float4*)asrc)[(size_t)v * 32 + c16 * 2 + 1];
            }
            unsigned o[4] = {pk_bf2(x0.x, x0.y), pk_bf2(x0.z, x0.w),
                             pk_bf2(x1.x, x1.y), pk_bf2(x1.z, x1.w)};
            *(uint4*)(sA16 + r * PS + c16 * 8) = *(uint4*)o;
        }
        #pragma unroll
        for (int it = 0; it < 8; it++) {
            int i = tx + it * 256;
            int r = i >> 4, c16 = i & 15;
            *(uint4*)(sB16 + r * PS + c16 * 8) = ((const uint4*)wsrc)[r * 16 + c16];
        }
        __syncthreads();
        mma_chunk(acc, aBase, bBase, lane, R0, C0);
        __syncthreads();
    }

    #pragma unroll
    for (int mt = 0; mt < 4; mt++) {
        int r0 = R0 + mt * 16 + g;
        #pragma unroll
        for (int nt = 0; nt < 4; nt++) {
            int col = C0 + nt * 8 + tig * 2;
            float bb0 = sb1[col], bb1 = sb1[col + 1];
            *(unsigned*)(sA16 + r0 * PS + col) =
                pk_bf2(silu_f(acc[mt][nt][0] + bb0), silu_f(acc[mt][nt][1] + bb1));
            *(unsigned*)(sA16 + (r0 + 8) * PS + col) =
                pk_bf2(silu_f(acc[mt][nt][2] + bb0), silu_f(acc[mt][nt][3] + bb1));
            #pragma unroll
            for (int q = 0; q < 4; q++) acc[mt][nt][q] = 0.f;
        }
    }
    #pragma unroll
    for (int it = 0; it < 8; it++) {
        int i = tx + it * 256;
        int r = i >> 4, c16 = i & 15;
        *(uint4*)(sB16 + r * PS + c16 * 8) = ((const uint4*)nw2b_l)[r * 16 + c16];
    }
    __syncthreads();
    mma_chunk(acc, aBase, bBase, lane, R0, C0);
    __syncthreads();

    #pragma unroll
    for (int mt = 0; mt < 4; mt++) {
        int r0 = R0 + mt * 16 + g;
        #pragma unroll
        for (int nt = 0; nt < 4; nt++) {
            int col = C0 + nt * 8 + tig * 2;
            *(float2*)(sX + r0 * 132 + col) = make_float2(acc[mt][nt][0], acc[mt][nt][1]);
            *(float2*)(sX + (r0 + 8) * 132 + col) = make_float2(acc[mt][nt][2], acc[mt][nt][3]);
        }
    }
    __syncthreads();

    #pragma unroll 1
    for (int rr = 0; rr < 16; rr++) {
        int row = wid5 * 16 + rr;
        int v = vbase + row;
        if (v >= V_N) break;
        float4 hv = ((const float4*)d_h)[(size_t)v * 32 + lane];
        float4 xn = *(float4*)(sX + row * 132 + lane * 4);
        float4 bb = *(float4*)(sb2 + lane * 4);
        float x0 = hv.x + xn.x + bb.x;
        float x1 = hv.y + xn.y + bb.y;
        float x2 = hv.z + xn.z + bb.z;
        float x3 = hv.w + xn.w + bb.w;
        float s1 = x0 + x1 + x2 + x3;
        #pragma unroll
        for (int off = 16; off; off >>= 1) s1 += __shfl_xor_sync(0xffffffffu, s1, off);
        float mu = s1 * (1.f / 128.f);
        float d0 = x0 - mu, d1 = x1 - mu, d2 = x2 - mu, d3 = x3 - mu;
        float s2 = d0 * d0 + d1 * d1 + d2 * d2 + d3 * d3;
        #pragma unroll
        for (int off = 16; off; off >>= 1) s2 += __shfl_xor_sync(0xffffffffu, s2, off);
        float rinv = rsqrtf(s2 * (1.f / 128.f) + LN_EPS);
        float4 gv = *(float4*)(sg + lane * 4);
        float4 bv = *(float4*)(sbb + lane * 4);
        float4 o;
        o.x = gv.x * d0 * rinv + bv.x;
        o.y = gv.y * d1 * rinv + bv.y;
        o.z = gv.z * d2 * rinv + bv.z;
        o.w = gv.w * d3 * rinv + bv.w;
        ((float4*)d_h)[(size_t)v * 32 + lane] = o;
    }
}

// ---------------- final loss ----------------
__global__ void k_loss(const float* __restrict__ pos0, const float* __restrict__ pos1,
                       const float* __restrict__ op_w, const float* __restrict__ op_b) {
    int lane = threadIdx.x & 31;
    int warp = threadIdx.x >> 5;
    int gw = blockIdx.x * 8 + warp;
    int nw = gridDim.x * 8;
    float local = 0.f;
    for (int v = gw; v < V_N; v += nw) {
        float s0 = 0.f, s1 = 0.f, s2 = 0.f;
        #pragma unroll
        for (int k = 0; k < 4; k++) {
            int c = lane + k * 32;
            float hv = d_h[(size_t)v * 128 + c];
            s0 = fmaf(hv, op_w[c * 3 + 0], s0);
            s1 = fmaf(hv, op_w[c * 3 + 1], s1);
            s2 = fmaf(hv, op_w[c * 3 + 2], s2);
        }
        #pragma unroll
        for (int off = 16; off; off >>= 1) {
            s0 += __shfl_xor_sync(0xffffffffu, s0, off);
            s1 += __shfl_xor_sync(0xffffffffu, s1, off);
            s2 += __shfl_xor_sync(0xffffffffu, s2, off);
        }
        if (lane == 0) {
            float d0 = s0 + op_b[0] - (pos1[v * 3 + 0] - pos0[v * 3 + 0]);
            float d1 = s1 + op_b[1] - (pos1[v * 3 + 1] - pos0[v * 3 + 1]);
            float d2 = s2 + op_b[2] - (pos1[v * 3 + 2] - pos0[v * 3 + 2]);
            local += d0 * d0 + d1 * d1 + d2 * d2;
        }
    }
    __shared__ float ws[8];
    if (lane == 0) ws[warp] = local;
    __syncthreads();
    if (threadIdx.x == 0) {
        float s = 0.f;
        for (int w = 0; w < 8; w++) s += ws[w];
        atomicAdd(&d_loss, s);
    }
}

__global__ void k_final(float* out) {
    out[0] = d_loss * (1.f / (3.f * (float)V_N));
}

// ---------------- launcher ----------------
extern "C" void kernel_launch(void* const* d_in, const int* in_sizes, int n_in,
                              void* d_out, int out_size) {
    const float* pos0  = (const float*)d_in[0];
    const float* pos1  = (const float*)d_in[1];
    const float* z     = (const float*)d_in[2];
    const float* t     = (const float*)d_in[3];
    const int*   ei    = (const int*)d_in[4];
    const int*   batch = (const int*)d_in[5];
    const float* te_w1 = (const float*)d_in[6];
    const float* te_b1 = (const float*)d_in[7];
    const float* te_w2 = (const float*)d_in[8];
    const float* te_b2 = (const float*)d_in[9];
    const float* cp_w  = (const float*)d_in[10];
    const float* cp_b  = (const float*)d_in[11];
    const float* ew1   = (const float*)d_in[12];
    const float* eb1   = (const float*)d_in[13];
    const float* ew2   = (const float*)d_in[14];
    const float* eb2   = (const float*)d_in[15];
    const float* nw1   = (const float*)d_in[16];
    const float* nb1   = (const float*)d_in[17];
    const float* nw2   = (const float*)d_in[18];
    const float* nb2   = (const float*)d_in[19];
    const float* ln_g  = (const float*)d_in[20];
    const float* ln_b  = (const float*)d_in[21];
    const float* op_w  = (const float*)d_in[22];
    const float* op_b  = (const float*)d_in[23];

    const int SMEM_PQ   = 128 * PS * 2 * 2;                                     // 69632
    const int SMEM_EDGE = 64 * PS * 2 + 128 * PS * 2 + (384 + 256) * 4 + 512 * 4 + 256 * 4; // 58368
    const int SMEM_NODE = 128 * PS * 2 * 2 + 4 * 128 * 4;                       // 71680

    cudaFuncSetAttribute(k_pq,   cudaFuncAttributeMaxDynamicSharedMemorySize, SMEM_PQ);
    cudaFuncSetAttribute(k_edge, cudaFuncAttributeMaxDynamicSharedMemorySize, SMEM_EDGE);
    cudaFuncSetAttribute(k_node, cudaFuncAttributeMaxDynamicSharedMemorySize, SMEM_NODE);

    __nv_bfloat16 *ew1b_base, *ew2b_base, *nw1b_base, *nw2b_base;
    cudaGetSymbolAddress((void**)&ew1b_base, d_ew1b);
    cudaGetSymbolAddress((void**)&ew2b_base, d_ew2b);
    cudaGetSymbolAddress((void**)&nw1b_base, d_nw1b);
    cudaGetSymbolAddress((void**)&nw2b_base, d_nw2b);

    // launch order: cvt(1), setup(2), pq(3), edge(4=ncu window)
    k_cvt<<<256, 256>>>(ew1, ew2, nw1, nw2);
    k_setup<<<1, 128>>>(t, te_w1, te_b1, te_w2, te_b2, z, cp_w, cp_b);

    int nodeblocks = (V_N + 127) / 128;  // 391
    for (int l = 0; l < 4; l++) {
        k_pq<<<nodeblocks, 256, SMEM_PQ>>>(ew1b_base + (size_t)l * 259 * 128,
                                           batch, pos0, pos1, t, (l == 0) ? 1 : 0);
        k_edge<<<E_N / (64 * EG), 256, SMEM_EDGE>>>(ei,
                                                    ew1 + (size_t)l * 259 * 128 + 256 * 128,
                                                    eb1 + l * 128,
                                                    eb2 + l * 128,
                                                    ew2b_base + (size_t)l * 128 * 128);
        k_node<<<nodeblocks, 256, SMEM_NODE>>>(nw1b_base + (size_t)l * 256 * 128, nb1 + l * 128,
                                               nw2b_base + (size_t)l * 128 * 128, nb2 + l * 128,
                                               ln_g + l * 128, ln_b + l * 128);
    }
    k_loss<<<592, 256>>>(pos0, pos1, op_w, op_b);
    k_final<<<1, 1>>>((float*)d_out);
}

// round 15
// speedup vs baseline: 1.1161x; 1.0186x over previous
#include <cuda_runtime.h>
#include <cuda_bf16.h>
#include <math.h>

#define V_N 50000
#define E_N 800000
#define B_N 8
#define H_N 128
#define LAT_N 64
#define TD_N 16
#define LN_EPS 1e-5f
#define PS 136   // padded bf16 row stride (272B) for 128-wide smem tiles
#define EG 4     // edge tiles (64 edges each) per block in k_edge

// ---- scratch (static device globals: allocation-free) ----
__device__ float d_h[(size_t)V_N * H_N];
__device__ float d_agg[(size_t)V_N * H_N];
__device__ float d_xt[(size_t)V_N * 3];
__device__ float d_zc[B_N * H_N];
__device__ float d_cvec[H_N];
__device__ float d_loss;
__device__ __nv_bfloat16 d_Pb[(size_t)V_N * H_N];
__device__ __nv_bfloat16 d_Qb[(size_t)V_N * H_N];
__device__ __nv_bfloat16 d_ew1b[4 * 259 * 128];
__device__ __nv_bfloat16 d_ew2b[4 * 128 * 128];
__device__ __nv_bfloat16 d_nw1b[4 * 256 * 128];
__device__ __nv_bfloat16 d_nw2b[4 * 128 * 128];

__device__ __forceinline__ float silu_f(float x) {
    return __fdividef(x, 1.0f + __expf(-x));
}
__device__ __forceinline__ unsigned pk_bf2(float a, float b) {
    __nv_bfloat162 t = __float22bfloat162_rn(make_float2(a, b));
    return *reinterpret_cast<unsigned*>(&t);
}

// ---------------- mma helpers ----------------
__device__ __forceinline__ void ldsm_x4(unsigned* r, unsigned addr) {
    asm volatile("ldmatrix.sync.aligned.m8n8.x4.shared.b16 {%0,%1,%2,%3}, [%4];"
                 : "=r"(r[0]), "=r"(r[1]), "=r"(r[2]), "=r"(r[3]) : "r"(addr));
}
__device__ __forceinline__ void ldsm_x2t(unsigned* r, unsigned addr) {
    asm volatile("ldmatrix.sync.aligned.m8n8.x2.trans.shared.b16 {%0,%1}, [%2];"
                 : "=r"(r[0]), "=r"(r[1]) : "r"(addr));
}
__device__ __forceinline__ void mma_bf16(float* c, const unsigned* a, const unsigned* b) {
    asm volatile("mma.sync.aligned.m16n8k16.row.col.f32.bf16.bf16.f32 "
                 "{%0,%1,%2,%3},{%4,%5,%6,%7},{%8,%9},{%0,%1,%2,%3};"
                 : "+f"(c[0]), "+f"(c[1]), "+f"(c[2]), "+f"(c[3])
                 : "r"(a[0]), "r"(a[1]), "r"(a[2]), "r"(a[3]), "r"(b[0]), "r"(b[1]));
}

// 128x128x128 bf16 GEMM chunk (8 warps, 64x32 warp tiles)
__device__ __forceinline__ void mma_chunk(float acc[4][4][4],
                                          unsigned aBase, unsigned bBase,
                                          int lane, int R0, int C0) {
    unsigned aRow[4], bCol[4];
    int l15 = lane & 15, lh = lane >> 4;
    #pragma unroll
    for (int mt = 0; mt < 4; mt++)
        aRow[mt] = aBase + (unsigned)((R0 + mt * 16 + l15) * PS + lh * 8) * 2u;
    #pragma unroll
    for (int nt = 0; nt < 4; nt++)
        bCol[nt] = bBase + (unsigned)(l15 * PS + C0 + nt * 8) * 2u;
    #pragma unroll
    for (int ks = 0; ks < 8; ks++) {
        unsigned a[4][4], b[4][2];
        #pragma unroll
        for (int mt = 0; mt < 4; mt++) ldsm_x4(a[mt], aRow[mt] + ks * 32);
        #pragma unroll
        for (int nt = 0; nt < 4; nt++) ldsm_x2t(b[nt], bCol[nt] + ks * (PS * 32));
        #pragma unroll
        for (int mt = 0; mt < 4; mt++)
            #pragma unroll
            for (int nt = 0; nt < 4; nt++)
                mma_bf16(acc[mt][nt], a[mt], b[nt]);
    }
}

// 64x128x128 bf16 GEMM chunk (8 warps, 32x32 warp tiles) — for k_edge
__device__ __forceinline__ void mma_chunk32(float acc[2][4][4],
                                            unsigned aBase, unsigned bBase,
                                            int lane, int R0, int C0) {
    unsigned aRow[2], bCol[4];
    int l15 = lane & 15, lh = lane >> 4;
    #pragma unroll
    for (int mt = 0; mt < 2; mt++)
        aRow[mt] = aBase + (unsigned)((R0 + mt * 16 + l15) * PS + lh * 8) * 2u;
    #pragma unroll
    for (int nt = 0; nt < 4; nt++)
        bCol[nt] = bBase + (unsigned)(l15 * PS + C0 + nt * 8) * 2u;
    #pragma unroll
    for (int ks = 0; ks < 8; ks++) {
        unsigned a[2][4], b[4][2];
        #pragma unroll
        for (int mt = 0; mt < 2; mt++) ldsm_x4(a[mt], aRow[mt] + ks * 32);
        #pragma unroll
        for (int nt = 0; nt < 4; nt++) ldsm_x2t(b[nt], bCol[nt] + ks * (PS * 32));
        #pragma unroll
        for (int mt = 0; mt < 2; mt++)
            #pragma unroll
            for (int nt = 0; nt < 4; nt++)
                mma_bf16(acc[mt][nt], a[mt], b[nt]);
    }
}

// ---------------- weight conversion (launch #1) ----------------
__global__ void k_cvt(const float* __restrict__ ew1, const float* __restrict__ ew2,
                      const float* __restrict__ nw1, const float* __restrict__ nw2) {
    int i0 = blockIdx.x * blockDim.x + threadIdx.x;
    int st = gridDim.x * blockDim.x;
    for (int i = i0; i < 4 * 259 * 128; i += st) d_ew1b[i] = __float2bfloat16(ew1[i]);
    for (int i = i0; i < 4 * 128 * 128; i += st) d_ew2b[i] = __float2bfloat16(ew2[i]);
    for (int i = i0; i < 4 * 256 * 128; i += st) d_nw1b[i] = __float2bfloat16(nw1[i]);
    for (int i = i0; i < 4 * 128 * 128; i += st) d_nw2b[i] = __float2bfloat16(nw2[i]);
}

// ---------------- setup: time embedding, cond-proj folding (launch #2) ----------------
__global__ void k_setup(const float* __restrict__ t,
                        const float* __restrict__ te_w1, const float* __restrict__ te_b1,
                        const float* __restrict__ te_w2, const float* __restrict__ te_b2,
                        const float* __restrict__ z,
                        const float* __restrict__ cp_w, const float* __restrict__ cp_b) {
    __shared__ float a_s[TD_N];
    __shared__ float temb[TD_N];
    int tx = threadIdx.x;  // 128 threads
    float ts = t[0];
    if (tx < TD_N) a_s[tx] = silu_f(ts * te_w1[tx] + te_b1[tx]);
    __syncthreads();
    if (tx < TD_N) {
        float acc = te_b2[tx];
        #pragma unroll
        for (int j = 0; j < TD_N; j++) acc += a_s[j] * te_w2[j * TD_N + tx];
        temb[tx] = acc;
    }
    __syncthreads();
    {
        float acc = cp_b[tx];
        #pragma unroll
        for (int j = 0; j < TD_N; j++) acc += temb[j] * cp_w[(LAT_N + j) * H_N + tx];
        d_cvec[tx] = acc;
    }
    for (int b = 0; b < B_N; b++) {
        float acc = 0.f;
        for (int k = 0; k < LAT_N; k++) acc += z[b * LAT_N + k] * cp_w[k * H_N + tx];
        d_zc[b * H_N + tx] = acc;
    }
    if (tx == 0) d_loss = 0.f;
}

// ---------------- k_pq (layer 0 only): P/Q + agg zero + h/xt init ----------------
__global__ __launch_bounds__(256, 2) void k_pq(const __nv_bfloat16* __restrict__ ew1b_l,
                                               const int* __restrict__ batch,
                                               const float* __restrict__ pos0,
                                               const float* __restrict__ pos1,
                                               const float* __restrict__ t) {
    extern __shared__ __align__(16) char sm_raw[];
    __nv_bfloat16* sA16 = (__nv_bfloat16*)sm_raw;
    __nv_bfloat16* sB16 = sA16 + 128 * PS;

    int tx = threadIdx.x;
    int vbase = blockIdx.x * 128;
    int lane = tx & 31, wid5 = tx >> 5;
    int R0 = (wid5 >> 2) * 64, C0 = (wid5 & 3) * 32;
    int g = lane >> 2, tig = lane & 3;

    // compute h0 = zc[batch] + cvec inline; write d_h; stage bf16 A
    #pragma unroll
    for (int it = 0; it < 8; it++) {
        int i = tx + it * 256;
        int r = i >> 4, c16 = i & 15;
        int v = vbase + r;
        float4 x0 = make_float4(0, 0, 0, 0), x1 = x0;
        if (v < V_N) {
            int b = batch[v];
            float4 z0 = ((const float4*)d_zc)[b * 32 + c16 * 2];
            float4 z1 = ((const float4*)d_zc)[b * 32 + c16 * 2 + 1];
            float4 c0 = ((const float4*)d_cvec)[c16 * 2];
            float4 c1 = ((const float4*)d_cvec)[c16 * 2 + 1];
            x0 = make_float4(z0.x + c0.x, z0.y + c0.y, z0.z + c0.z, z0.w + c0.w);
            x1 = make_float4(z1.x + c1.x, z1.y + c1.y, z1.z + c1.z, z1.w + c1.w);
            ((float4*)d_h)[(size_t)v * 32 + c16 * 2] = x0;
            ((float4*)d_h)[(size_t)v * 32 + c16 * 2 + 1] = x1;
        }
        unsigned o[4] = {pk_bf2(x0.x, x0.y), pk_bf2(x0.z, x0.w),
                         pk_bf2(x1.x, x1.y), pk_bf2(x1.z, x1.w)};
        *(uint4*)(sA16 + r * PS + c16 * 8) = *(uint4*)o;
    }
    if (tx < 128) {
        int v = vbase + tx;
        if (v < V_N) {
            float ts = t[0];
            #pragma unroll
            for (int c = 0; c < 3; c++)
                d_xt[v * 3 + c] = (1.f - ts) * pos0[v * 3 + c] + ts * pos1[v * 3 + c];
        }
    }
    #pragma unroll
    for (int it = 0; it < 8; it++) {
        int i = tx + it * 256;
        int r = i >> 4, c16 = i & 15;
        *(uint4*)(sB16 + r * PS + c16 * 8) = ((const uint4*)ew1b_l)[r * 16 + c16];
    }
    __syncthreads();

    unsigned aBase = (unsigned)__cvta_generic_to_shared(sA16);
    unsigned bBase = (unsigned)__cvta_generic_to_shared(sB16);

    float acc[4][4][4];
    #pragma unroll
    for (int mt = 0; mt < 4; mt++)
        #pragma unroll
        for (int nt = 0; nt < 4; nt++)
            #pragma unroll
            for (int q = 0; q < 4; q++) acc[mt][nt][q] = 0.f;
    mma_chunk(acc, aBase, bBase, lane, R0, C0);
    __syncthreads();

    #pragma unroll
    for (int mt = 0; mt < 4; mt++) {
        int r0 = R0 + mt * 16 + g;
        int v0 = vbase + r0, v1 = v0 + 8;
        #pragma unroll
        for (int nt = 0; nt < 4; nt++) {
            int col = C0 + nt * 8 + tig * 2;
            if (v0 < V_N) *(unsigned*)(d_Pb + (size_t)v0 * 128 + col) = pk_bf2(acc[mt][nt][0], acc[mt][nt][1]);
            if (v1 < V_N) *(unsigned*)(d_Pb + (size_t)v1 * 128 + col) = pk_bf2(acc[mt][nt][2], acc[mt][nt][3]);
            #pragma unroll
            for (int q = 0; q < 4; q++) acc[mt][nt][q] = 0.f;
        }
    }
    const __nv_bfloat16* w1b = ew1b_l + 128 * 128;
    #pragma unroll
    for (int it = 0; it < 8; it++) {
        int i = tx + it * 256;
        int r = i >> 4, c16 = i & 15;
        *(uint4*)(sB16 + r * PS + c16 * 8) = ((const uint4*)w1b)[r * 16 + c16];
    }
    __syncthreads();
    mma_chunk(acc, aBase, bBase, lane, R0, C0);

    #pragma unroll
    for (int mt = 0; mt < 4; mt++) {
        int r0 = R0 + mt * 16 + g;
        int v0 = vbase + r0, v1 = v0 + 8;
        #pragma unroll
        for (int nt = 0; nt < 4; nt++) {
            int col = C0 + nt * 8 + tig * 2;
            if (v0 < V_N) *(unsigned*)(d_Qb + (size_t)v0 * 128 + col) = pk_bf2(acc[mt][nt][0], acc[mt][nt][1]);
            if (v1 < V_N) *(unsigned*)(d_Qb + (size_t)v1 * 128 + col) = pk_bf2(acc[mt][nt][2], acc[mt][nt][3]);
        }
    }
    #pragma unroll
    for (int it = 0; it < 16; it++) {
        int i = tx + it * 256;
        int r = i >> 5, c4 = i & 31;
        int v = vbase + r;
        if (v < V_N) ((float4*)d_agg)[(size_t)v * 32 + c4] = make_float4(0, 0, 0, 0);
    }
}

// ---------------- k_edge: EG x 64-edge tiles; W2 once; pipelined index prefetch ----------------
__global__ __launch_bounds__(256, 3) void k_edge(const int* __restrict__ ei,
                                                 const float* __restrict__ w1c,
                                                 const float* __restrict__ b1,
                                                 const float* __restrict__ b2,
                                                 const __nv_bfloat16* __restrict__ w2b) {
    extern __shared__ __align__(16) char sm_raw[];
    __nv_bfloat16* sU16 = (__nv_bfloat16*)sm_raw;       // 64 x PS
    __nv_bfloat16* sB16 = sU16 + 64 * PS;               // 128 x PS
    float* sw1c = (float*)(sB16 + 128 * PS);            // 384
    float* sb1  = sw1c + 384;                           // 128
    float* sb2  = sb1 + 128;                            // 128
    float* sdp  = sb2 + 128;                            // 2 x 256 (double-buffered)
    int*   sdst = (int*)(sdp + 512);                    // 2 x 64
    int*   ssrc = sdst + 128;                           // 2 x 64

    int tx = threadIdx.x;
    int lane = tx & 31, wid5 = tx >> 5;
    int R0 = (wid5 >> 2) * 32, C0 = (wid5 & 3) * 32;
    int g = lane >> 2, tig = lane & 3;

    if (tx < 128) {
        sb1[tx] = b1[tx]; sb2[tx] = b2[tx];
        sw1c[tx] = w1c[tx];
        sw1c[128 + tx] = w1c[128 + tx];
        sw1c[256 + tx] = w1c[256 + tx];
    }
    #pragma unroll
    for (int it = 0; it < 8; it++) {
        int i = tx + it * 256;
        int r = i >> 4, c16 = i & 15;
        *(uint4*)(sB16 + r * PS + c16 * 8) = ((const uint4*)w2b)[r * 16 + c16];
    }
    // prefetch tile 0 indices
    if (tx < 64) {
        int e = blockIdx.x * EG * 64 + tx;
        int s = ei[e];
        int d = ei[E_N + e];
        ssrc[tx] = s; sdst[tx] = d;
        sdp[tx * 4 + 0] = d_xt[d * 3 + 0] - d_xt[s * 3 + 0];
        sdp[tx * 4 + 1] = d_xt[d * 3 + 1] - d_xt[s * 3 + 1];
        sdp[tx * 4 + 2] = d_xt[d * 3 + 2] - d_xt[s * 3 + 2];
    }
    __syncthreads();

    unsigned aBase = (unsigned)__cvta_generic_to_shared(sU16);
    unsigned bBase = (unsigned)__cvta_generic_to_shared(sB16);

    for (int gtile = 0; gtile < EG; gtile++) {
        int cur = gtile & 1, nxt = cur ^ 1;
        const int* cdst = sdst + cur * 64;
        const int* csrc = ssrc + cur * 64;
        const float* cdp = sdp + cur * 256;

        // gather + fused first layer: U = silu(P[dst] + Q[src] + dpos@W1c + b1)
        #pragma unroll
        for (int it = 0; it < 4; it++) {
            int i = tx + it * 256;
            int e = i >> 4, c16 = i & 15;
            int c = c16 * 8;
            uint4 pv = *(const uint4*)(d_Pb + (size_t)cdst[e] * 128 + c);
            uint4 qv = *(const uint4*)(d_Qb + (size_t)csrc[e] * 128 + c);
            __nv_bfloat162* pp = (__nv_bfloat162*)&pv;
            __nv_bfloat162* qq = (__nv_bfloat162*)&qv;
            float dx = cdp[e * 4], dy = cdp[e * 4 + 1], dz = cdp[e * 4 + 2];
            float u[8];
            #pragma unroll
            for (int j = 0; j < 4; j++) {
                float2 pf = __bfloat1622float2(pp[j]);
                float2 qf = __bfloat1622float2(qq[j]);
                int cc = c + j * 2;
                u[j * 2 + 0] = pf.x + qf.x + dx * sw1c[cc] + dy * sw1c[128 + cc] + dz * sw1c[256 + cc] + sb1[cc];
                u[j * 2 + 1] = pf.y + qf.y + dx * sw1c[cc + 1] + dy * sw1c[128 + cc + 1] + dz * sw1c[256 + cc + 1] + sb1[cc + 1];
            }
            unsigned o[4];
            #pragma unroll
            for (int j = 0; j < 4; j++)
                o[j] = pk_bf2(silu_f(u[j * 2]), silu_f(u[j * 2 + 1]));
            *(uint4*)(sU16 + e * PS + c) = *(uint4*)o;
        }
        __syncthreads();

        // prefetch next tile's indices/dpos into the other buffer (overlaps mma)
        if (gtile + 1 < EG && tx < 64) {
            int e = (blockIdx.x * EG + gtile + 1) * 64 + tx;
            int s = ei[e];
            int d = ei[E_N + e];
            ssrc[nxt * 64 + tx] = s; sdst[nxt * 64 + tx] = d;
            sdp[nxt * 256 + tx * 4 + 0] = d_xt[d * 3 + 0] - d_xt[s * 3 + 0];
            sdp[nxt * 256 + tx * 4 + 1] = d_xt[d * 3 + 1] - d_xt[s * 3 + 1];
            sdp[nxt * 256 + tx * 4 + 2] = d_xt[d * 3 + 2] - d_xt[s * 3 + 2];
        }

        float acc[2][4][4];
        #pragma unroll
        for (int mt = 0; mt < 2; mt++)
            #pragma unroll
            for (int nt = 0; nt < 4; nt++)
                #pragma unroll
                for (int q = 0; q < 4; q++) acc[mt][nt][q] = 0.f;
        mma_chunk32(acc, aBase, bBase, lane, R0, C0);

        // epilogue: silu + v2 REDs into agg
        #pragma unroll
        for (int mt = 0; mt < 2; mt++) {
            int r0 = R0 + mt * 16 + g;
            int d0 = cdst[r0], d1 = cdst[r0 + 8];
            #pragma unroll
            for (int nt = 0; nt < 4; nt++) {
                int col = C0 + nt * 8 + tig * 2;
                float bb0 = sb2[col], bb1 = sb2[col + 1];
                float m0 = silu_f(acc[mt][nt][0] + bb0);
                float m1 = silu_f(acc[mt][nt][1] + bb1);
                float m2 = silu_f(acc[mt][nt][2] + bb0);
                float m3 = silu_f(acc[mt][nt][3] + bb1);
                float* pA = d_agg + (size_t)d0 * 128 + col;
                float* pB = d_agg + (size_t)d1 * 128 + col;
                asm volatile("red.global.add.v2.f32 [%0], {%1,%2};" :: "l"(pA), "f"(m0), "f"(m1) : "memory");
                asm volatile("red.global.add.v2.f32 [%0], {%1,%2};" :: "l"(pB), "f"(m2), "f"(m3) : "memory");
            }
        }
        __syncthreads();   // mma readers + prefetch done before next U-build overwrites sU16
    }
}

// ---------------- k_node: MLP + residual + LayerNorm + fused next-layer P/Q ----------------
__global__ __launch_bounds__(256, 2) void k_node(const __nv_bfloat16* __restrict__ nw1b_l,
                                                 const float* __restrict__ nb1l,
                                                 const __nv_bfloat16* __restrict__ nw2b_l,
                                                 const float* __restrict__ nb2l,
                                                 const float* __restrict__ lngl,
                                                 const float* __restrict__ lnbl,
                                                 const __nv_bfloat16* __restrict__ ew1b_next) {
    extern __shared__ __align__(16) char sm_raw[];
    __nv_bfloat16* sA16 = (__nv_bfloat16*)sm_raw;           // 128 x PS
    __nv_bfloat16* sB16 = sA16 + 128 * PS;                  // 128 x PS
    float* sPar = (float*)(sB16 + 128 * PS);                // 4 x 128
    float* sb1 = sPar, * sb2 = sPar + 128, * sg = sPar + 256, * sbb = sPar + 384;

    int tx = threadIdx.x;
    int vbase = blockIdx.x * 128;
    int lane = tx & 31, wid5 = tx >> 5;
    int R0 = (wid5 >> 2) * 64, C0 = (wid5 & 3) * 32;
    int g = lane >> 2, tig = lane & 3;

    if (tx < 128) { sb1[tx] = nb1l[tx]; sb2[tx] = nb2l[tx]; sg[tx] = lngl[tx]; sbb[tx] = lnbl[tx]; }

    unsigned aBase = (unsigned)__cvta_generic_to_shared(sA16);
    unsigned bBase = (unsigned)__cvta_generic_to_shared(sB16);

    float acc[4][4][4];
    #pragma unroll
    for (int mt = 0; mt < 4; mt++)
        #pragma unroll
        for (int nt = 0; nt < 4; nt++)
            #pragma unroll
            for (int q = 0; q < 4; q++) acc[mt][nt][q] = 0.f;

    // GEMM1 over K=256: chunk0 = h, chunk1 = agg
    for (int chunk = 0; chunk < 2; chunk++) {
        const float* asrc = chunk ? d_agg : d_h;
        const __nv_bfloat16* wsrc = nw1b_l + chunk * (128 * 128);
        #pragma unroll
        for (int it = 0; it < 8; it++) {
            int i = tx + it * 256;
            int r = i >> 4, c16 = i & 15;
            int v = vbase + r;
            float4 x0 = make_float4(0, 0, 0, 0), x1 = x0;
            if (v < V_N) {
                x0 = ((const float4*)asrc)[(size_t)v * 32 + c16 * 2];
                x1 = ((const float4*)asrc)[(size_t)v * 32 + c16 * 2 + 1];
            }
            unsigned o[4] = {pk_bf2(x0.x, x0.y), pk_bf2(x0.z, x0.w),
                             pk_bf2(x1.x, x1.y), pk_bf2(x1.z, x1.w)};
            *(uint4*)(sA16 + r * PS + c16 * 8) = *(uint4*)o;
        }
        #pragma unroll
        for (int it = 0; it < 8; it++) {
            int i = tx + it * 256;
            int r = i >> 4, c16 = i & 15;
            *(uint4*)(sB16 + r * PS + c16 * 8) = ((const uint4*)wsrc)[r * 16 + c16];
        }
        __syncthreads();
        mma_chunk(acc, aBase, bBase, lane, R0, C0);
        __syncthreads();
    }

    // U = silu(acc + b1) -> sA16 (bf16); B <- nw2
    #pragma unroll
    for (int mt = 0; mt < 4; mt++) {
        int r0 = R0 + mt * 16 + g;
        #pragma unroll
        for (int nt = 0; nt < 4; nt++) {
            int col = C0 + nt * 8 + tig * 2;
            float bb0 = sb1[col], bb1 = sb1[col + 1];
            *(unsigned*)(sA16 + r0 * PS + col) =
                pk_bf2(silu_f(acc[mt][nt][0] + bb0), silu_f(acc[mt][nt][1] + bb1));
            *(unsigned*)(sA16 + (r0 + 8) * PS + col) =
                pk_bf2(silu_f(acc[mt][nt][2] + bb0), silu_f(acc[mt][nt][3] + bb1));
            #pragma unroll
            for (int q = 0; q < 4; q++) acc[mt][nt][q] = 0.f;
        }
    }
    #pragma unroll
    for (int it = 0; it < 8; it++) {
        int i = tx + it * 256;
        int r = i >> 4, c16 = i & 15;
        *(uint4*)(sB16 + r * PS + c16 * 8) = ((const uint4*)nw2b_l)[r * 16 + c16];
    }
    __syncthreads();
    mma_chunk(acc, aBase, bBase, lane, R0, C0);
    __syncthreads();   // done reading sA16 (U)

    // spill h_new (bf16) into sA16
    #pragma unroll
    for (int mt = 0; mt < 4; mt++) {
        int r0 = R0 + mt * 16 + g;
        #pragma unroll
        for (int nt = 0; nt < 4; nt++) {
            int col = C0 + nt * 8 + tig * 2;
            *(unsigned*)(sA16 + r0 * PS + col) = pk_bf2(acc[mt][nt][0], acc[mt][nt][1]);
            *(unsigned*)(sA16 + (r0 + 8) * PS + col) = pk_bf2(acc[mt][nt][2], acc[mt][nt][3]);
        }
    }
    __syncthreads();

    // residual + LayerNorm; write d_h AND normalized bf16 h back into sA16 in-place
    #pragma unroll 1
    for (int rr = 0; rr < 16; rr++) {
        int row = wid5 * 16 + rr;
        int v = vbase + row;
        if (v >= V_N) break;
        float4 hv = ((const float4*)d_h)[(size_t)v * 32 + lane];
        uint2 hb = *(uint2*)(sA16 + row * PS + lane * 4);
        float2 xa = __bfloat1622float2(*(__nv_bfloat162*)&hb.x);
        float2 xbv = __bfloat1622float2(*(__nv_bfloat162*)&hb.y);
        float4 bb = *(float4*)(sb2 + lane * 4);
        float x0 = hv.x + xa.x + bb.x;
        float x1 = hv.y + xa.y + bb.y;
        float x2 = hv.z + xbv.x + bb.z;
        float x3 = hv.w + xbv.y + bb.w;
        float s1 = x0 + x1 + x2 + x3;
        #pragma unroll
        for (int off = 16; off; off >>= 1) s1 += __shfl_xor_sync(0xffffffffu, s1, off);
        float mu = s1 * (1.f / 128.f);
        float d0 = x0 - mu, d1 = x1 - mu, d2 = x2 - mu, d3 = x3 - mu;
        float s2 = d0 * d0 + d1 * d1 + d2 * d2 + d3 * d3;
        #pragma unroll
        for (int off = 16; off; off >>= 1) s2 += __shfl_xor_sync(0xffffffffu, s2, off);
        float rinv = rsqrtf(s2 * (1.f / 128.f) + LN_EPS);
        float4 gv = *(float4*)(sg + lane * 4);
        float4 bv = *(float4*)(sbb + lane * 4);
        float4 o;
        o.x = gv.x * d0 * rinv + bv.x;
        o.y = gv.y * d1 * rinv + bv.y;
        o.z = gv.z * d2 * rinv + bv.z;
        o.w = gv.w * d3 * rinv + bv.w;
        ((float4*)d_h)[(size_t)v * 32 + lane] = o;
        uint2 ob;
        ob.x = pk_bf2(o.x, o.y);
        ob.y = pk_bf2(o.z, o.w);
        *(uint2*)(sA16 + row * PS + lane * 4) = ob;
    }

    // ---- fused next-layer P/Q + agg zeroing ----
    if (ew1b_next) {
        __syncthreads();   // sA16 holds normalized h bf16
        #pragma unroll
        for (int it = 0; it < 8; it++) {
            int i = tx + it * 256;
            int r = i >> 4, c16 = i & 15;
            *(uint4*)(sB16 + r * PS + c16 * 8) = ((const uint4*)ew1b_next)[r * 16 + c16];
        }
        __syncthreads();

        #pragma unroll
        for (int mt = 0; mt < 4; mt++)
            #pragma unroll
            for (int nt = 0; nt < 4; nt++)
                #pragma unroll
                for (int q = 0; q < 4; q++) acc[mt][nt][q] = 0.f;
        mma_chunk(acc, aBase, bBase, lane, R0, C0);
        __syncthreads();

        #pragma unroll
        for (int mt = 0; mt < 4; mt++) {
            int r0 = R0 + mt * 16 + g;
            int v0 = vbase + r0, v1 = v0 + 8;
            #pragma unroll
            for (int nt = 0; nt < 4; nt++) {
                int col = C0 + nt * 8 + tig * 2;
                if (v0 < V_N) *(unsigned*)(d_Pb + (size_t)v0 * 128 + col) = pk_bf2(acc[mt][nt][0], acc[mt][nt][1]);
                if (v1 < V_N) *(unsigned*)(d_Pb + (size_t)v1 * 128 + col) = pk_bf2(acc[mt][nt][2], acc[mt][nt][3]);
                #pragma unroll
                for (int q = 0; q < 4; q++) acc[mt][nt][q] = 0.f;
            }
        }
        const __nv_bfloat16* w1b = ew1b_next + 128 * 128;
        #pragma unroll
        for (int it = 0; it < 8; it++) {
            int i = tx + it * 256;
            int r = i >> 4, c16 = i & 15;
            *(uint4*)(sB16 + r * PS + c16 * 8) = ((const uint4*)w1b)[r * 16 + c16];
        }
        __syncthreads();
        mma_chunk(acc, aBase, bBase, lane, R0, C0);

        #pragma unroll
        for (int mt = 0; mt < 4; mt++) {
            int r0 = R0 + mt * 16 + g;
            int v0 = vbase + r0, v1 = v0 + 8;
            #pragma unroll
            for (int nt = 0; nt < 4; nt++) {
                int col = C0 + nt * 8 + tig * 2;
                if (v0 < V_N) *(unsigned*)(d_Qb + (size_t)v0 * 128 + col) = pk_bf2(acc[mt][nt][0], acc[mt][nt][1]);
                if (v1 < V_N) *(unsigned*)(d_Qb + (size_t)v1 * 128 + col) = pk_bf2(acc[mt][nt][2], acc[mt][nt][3]);
            }
        }
        #pragma unroll
        for (int it = 0; it < 16; it++) {
            int i = tx + it * 256;
            int r = i >> 5, c4 = i & 31;
            int v = vbase + r;
            if (v < V_N) ((float4*)d_agg)[(size_t)v * 32 + c4] = make_float4(0, 0, 0, 0);
        }
    }
}

// ---------------- final loss ----------------
__global__ void k_loss(const float* __restrict__ pos0, const float* __restrict__ pos1,
                       const float* __restrict__ op_w, const float* __restrict__ op_b) {
    int lane = threadIdx.x & 31;
    int warp = threadIdx.x >> 5;
    int gw = blockIdx.x * 8 + warp;
    int nw = gridDim.x * 8;
    float local = 0.f;
    for (int v = gw; v < V_N; v += nw) {
        float s0 = 0.f, s1 = 0.f, s2 = 0.f;
        #pragma unroll
        for (int k = 0; k < 4; k++) {
            int c = lane + k * 32;
            float hv = d_h[(size_t)v * 128 + c];
            s0 = fmaf(hv, op_w[c * 3 + 0], s0);
            s1 = fmaf(hv, op_w[c * 3 + 1], s1);
            s2 = fmaf(hv, op_w[c * 3 + 2], s2);
        }
        #pragma unroll
        for (int off = 16; off; off >>= 1) {
            s0 += __shfl_xor_sync(0xffffffffu, s0, off);
            s1 += __shfl_xor_sync(0xffffffffu, s1, off);
            s2 += __shfl_xor_sync(0xffffffffu, s2, off);
        }
        if (lane == 0) {
            float d0 = s0 + op_b[0] - (pos1[v * 3 + 0] - pos0[v * 3 + 0]);
            float d1 = s1 + op_b[1] - (pos1[v * 3 + 1] - pos0[v * 3 + 1]);
            float d2 = s2 + op_b[2] - (pos1[v * 3 + 2] - pos0[v * 3 + 2]);
            local += d0 * d0 + d1 * d1 + d2 * d2;
        }
    }
    __shared__ float ws[8];
    if (lane == 0) ws[warp] = local;
    __syncthreads();
    if (threadIdx.x == 0) {
        float s = 0.f;
        for (int w = 0; w < 8; w++) s += ws[w];
        atomicAdd(&d_loss, s);
    }
}

__global__ void k_final(float* out) {
    out[0] = d_loss * (1.f / (3.f * (float)V_N));
}

// ---------------- launcher ----------------
extern "C" void kernel_launch(void* const* d_in, const int* in_sizes, int n_in,
                              void* d_out, int out_size) {
    const float* pos0  = (const float*)d_in[0];
    const float* pos1  = (const float*)d_in[1];
    const float* z     = (const float*)d_in[2];
    const float* t     = (const float*)d_in[3];
    const int*   ei    = (const int*)d_in[4];
    const int*   batch = (const int*)d_in[5];
    const float* te_w1 = (const float*)d_in[6];
    const float* te_b1 = (const float*)d_in[7];
    const float* te_w2 = (const float*)d_in[8];
    const float* te_b2 = (const float*)d_in[9];
    const float* cp_w  = (const float*)d_in[10];
    const float* cp_b  = (const float*)d_in[11];
    const float* ew1   = (const float*)d_in[12];
    const float* eb1   = (const float*)d_in[13];
    const float* ew2   = (const float*)d_in[14];
    const float* eb2   = (const float*)d_in[15];
    const float* nw1   = (const float*)d_in[16];
    const float* nb1   = (const float*)d_in[17];
    const float* nw2   = (const float*)d_in[18];
    const float* nb2   = (const float*)d_in[19];
    const float* ln_g  = (const float*)d_in[20];
    const float* ln_b  = (const float*)d_in[21];
    const float* op_w  = (const float*)d_in[22];
    const float* op_b  = (const float*)d_in[23];

    const int SMEM_PQ   = 128 * PS * 2 * 2;                                     // 69632
    const int SMEM_EDGE = 64 * PS * 2 + 128 * PS * 2 + (384 + 256) * 4 + 512 * 4 + 256 * 4; // 58368
    const int SMEM_NODE = 128 * PS * 2 * 2 + 4 * 128 * 4;                       // 71680

    cudaFuncSetAttribute(k_pq,   cudaFuncAttributeMaxDynamicSharedMemorySize, SMEM_PQ);
    cudaFuncSetAttribute(k_edge, cudaFuncAttributeMaxDynamicSharedMemorySize, SMEM_EDGE);
    cudaFuncSetAttribute(k_node, cudaFuncAttributeMaxDynamicSharedMemorySize, SMEM_NODE);

    __nv_bfloat16 *ew1b_base, *ew2b_base, *nw1b_base, *nw2b_base;
    cudaGetSymbolAddress((void**)&ew1b_base, d_ew1b);
    cudaGetSymbolAddress((void**)&ew2b_base, d_ew2b);
    cudaGetSymbolAddress((void**)&nw1b_base, d_nw1b);
    cudaGetSymbolAddress((void**)&nw2b_base, d_nw2b);

    // launch order: cvt(1), setup(2), pq(3), edge(4=ncu window)
    k_cvt<<<256, 256>>>(ew1, ew2, nw1, nw2);
    k_setup<<<1, 128>>>(t, te_w1, te_b1, te_w2, te_b2, z, cp_w, cp_b);

    int nodeblocks = (V_N + 127) / 128;  // 391
    k_pq<<<nodeblocks, 256, SMEM_PQ>>>(ew1b_base, batch, pos0, pos1, t);
    for (int l = 0; l < 4; l++) {
        k_edge<<<E_N / (64 * EG), 256, SMEM_EDGE>>>(ei,
                                                    ew1 + (size_t)l * 259 * 128 + 256 * 128,
                                                    eb1 + l * 128,
                                                    eb2 + l * 128,
                                                    ew2b_base + (size_t)l * 128 * 128);
        const __nv_bfloat16* nxt = (l < 3) ? (ew1b_base + (size_t)(l + 1) * 259 * 128)
                                           : (const __nv_bfloat16*)nullptr;
        k_node<<<nodeblocks, 256, SMEM_NODE>>>(nw1b_base + (size_t)l * 256 * 128, nb1 + l * 128,
                                               nw2b_base + (size_t)l * 128 * 128, nb2 + l * 128,
                                               ln_g + l * 128, ln_b + l * 128, nxt);
    }
    k_loss<<<592, 256>>>(pos0, pos1, op_w, op_b);
    k_final<<<1, 1>>>((float*)d_out);
}